// round 1
// baseline (speedup 1.0000x reference)
#include <cuda_runtime.h>
#include <math.h>

#define BATCH 4
#define SEQ   2048
#define DM    1024

// Scratch: Q, K, V (32 MB each) + scores (64 MB). __device__ globals per allocation rules.
__device__ float g_q[(size_t)BATCH * SEQ * DM];
__device__ float g_k[(size_t)BATCH * SEQ * DM];
__device__ float g_v[(size_t)BATCH * SEQ * DM];
__device__ float g_s[(size_t)BATCH * SEQ * SEQ];

// ---------------------------------------------------------------------------
// Batched C = A @ B (+ bias), A[M,K] row-major, B[K,N] row-major.
// 128x128 tile, K-step 8, 256 threads, 8x8 per-thread microtile.
// ---------------------------------------------------------------------------
__global__ __launch_bounds__(256) void gemm_nn(
    const float* __restrict__ A, const float* __restrict__ Bm,
    const float* __restrict__ bias, float* __restrict__ C,
    int M, int N, int K, size_t sA, size_t sB, size_t sC)
{
    __shared__ float As[8][132];   // +4 pad: conflict-free transposed stores
    __shared__ float Bs[8][132];

    A  += (size_t)blockIdx.z * sA;
    Bm += (size_t)blockIdx.z * sB;
    C  += (size_t)blockIdx.z * sC;

    const int tid = threadIdx.x;
    const int tx = tid & 15, ty = tid >> 4;
    const int m0 = blockIdx.y * 128, n0 = blockIdx.x * 128;

    // A tile: 128 rows x 8 cols = 256 float4 (one per thread), stored transposed
    const int a_row = tid >> 1, a_col = (tid & 1) * 4;
    // B tile: 8 rows x 128 cols = 256 float4 (one per thread)
    const int b_row = tid >> 5, b_col = (tid & 31) * 4;

    float acc[8][8] = {};

    for (int k0 = 0; k0 < K; k0 += 8) {
        float4 av = *reinterpret_cast<const float4*>(A  + (size_t)(m0 + a_row) * K + k0 + a_col);
        float4 bv = *reinterpret_cast<const float4*>(Bm + (size_t)(k0 + b_row) * N + n0 + b_col);
        __syncthreads();
        As[a_col + 0][a_row] = av.x;
        As[a_col + 1][a_row] = av.y;
        As[a_col + 2][a_row] = av.z;
        As[a_col + 3][a_row] = av.w;
        *reinterpret_cast<float4*>(&Bs[b_row][b_col]) = bv;
        __syncthreads();

        #pragma unroll
        for (int k = 0; k < 8; k++) {
            float4 a0 = *reinterpret_cast<const float4*>(&As[k][ty * 8]);
            float4 a1 = *reinterpret_cast<const float4*>(&As[k][ty * 8 + 4]);
            float4 b0 = *reinterpret_cast<const float4*>(&Bs[k][tx * 8]);
            float4 b1 = *reinterpret_cast<const float4*>(&Bs[k][tx * 8 + 4]);
            float ar[8] = {a0.x, a0.y, a0.z, a0.w, a1.x, a1.y, a1.z, a1.w};
            float br[8] = {b0.x, b0.y, b0.z, b0.w, b1.x, b1.y, b1.z, b1.w};
            #pragma unroll
            for (int i = 0; i < 8; i++)
                #pragma unroll
                for (int j = 0; j < 8; j++)
                    acc[i][j] = fmaf(ar[i], br[j], acc[i][j]);
        }
    }

    #pragma unroll
    for (int i = 0; i < 8; i++) {
        const size_t m = (size_t)(m0 + ty * 8 + i);
        #pragma unroll
        for (int j = 0; j < 8; j += 4) {
            const int n = n0 + tx * 8 + j;
            float4 o;
            o.x = acc[i][j + 0];
            o.y = acc[i][j + 1];
            o.z = acc[i][j + 2];
            o.w = acc[i][j + 3];
            if (bias) {
                o.x += bias[n];
                o.y += bias[n + 1];
                o.z += bias[n + 2];
                o.w += bias[n + 3];
            }
            *reinterpret_cast<float4*>(C + m * N + n) = o;
        }
    }
}

// ---------------------------------------------------------------------------
// Batched C = scale * (A @ B^T), A[M,K], B[N,K] both row-major (scores kernel).
// ---------------------------------------------------------------------------
__global__ __launch_bounds__(256) void gemm_nt_scaled(
    const float* __restrict__ A, const float* __restrict__ Bm,
    float* __restrict__ C, int M, int N, int K, float scale,
    size_t sA, size_t sB, size_t sC)
{
    __shared__ float As[8][132];
    __shared__ float Bs[8][132];

    A  += (size_t)blockIdx.z * sA;
    Bm += (size_t)blockIdx.z * sB;
    C  += (size_t)blockIdx.z * sC;

    const int tid = threadIdx.x;
    const int tx = tid & 15, ty = tid >> 4;
    const int m0 = blockIdx.y * 128, n0 = blockIdx.x * 128;

    // Both tiles are 128 rows x 8 K-cols
    const int r = tid >> 1, c = (tid & 1) * 4;

    float acc[8][8] = {};

    for (int k0 = 0; k0 < K; k0 += 8) {
        float4 av = *reinterpret_cast<const float4*>(A  + (size_t)(m0 + r) * K + k0 + c);
        float4 bv = *reinterpret_cast<const float4*>(Bm + (size_t)(n0 + r) * K + k0 + c);
        __syncthreads();
        As[c + 0][r] = av.x;  As[c + 1][r] = av.y;
        As[c + 2][r] = av.z;  As[c + 3][r] = av.w;
        Bs[c + 0][r] = bv.x;  Bs[c + 1][r] = bv.y;
        Bs[c + 2][r] = bv.z;  Bs[c + 3][r] = bv.w;
        __syncthreads();

        #pragma unroll
        for (int k = 0; k < 8; k++) {
            float4 a0 = *reinterpret_cast<const float4*>(&As[k][ty * 8]);
            float4 a1 = *reinterpret_cast<const float4*>(&As[k][ty * 8 + 4]);
            float4 b0 = *reinterpret_cast<const float4*>(&Bs[k][tx * 8]);
            float4 b1 = *reinterpret_cast<const float4*>(&Bs[k][tx * 8 + 4]);
            float ar[8] = {a0.x, a0.y, a0.z, a0.w, a1.x, a1.y, a1.z, a1.w};
            float br[8] = {b0.x, b0.y, b0.z, b0.w, b1.x, b1.y, b1.z, b1.w};
            #pragma unroll
            for (int i = 0; i < 8; i++)
                #pragma unroll
                for (int j = 0; j < 8; j++)
                    acc[i][j] = fmaf(ar[i], br[j], acc[i][j]);
        }
    }

    #pragma unroll
    for (int i = 0; i < 8; i++) {
        const size_t m = (size_t)(m0 + ty * 8 + i);
        #pragma unroll
        for (int j = 0; j < 8; j += 4) {
            const int n = n0 + tx * 8 + j;
            float4 o;
            o.x = acc[i][j + 0] * scale;
            o.y = acc[i][j + 1] * scale;
            o.z = acc[i][j + 2] * scale;
            o.w = acc[i][j + 3] * scale;
            *reinterpret_cast<float4*>(C + m * N + n) = o;
        }
    }
}

// ---------------------------------------------------------------------------
// In-place row softmax, n = 2048 fixed, one block (256 thr) per row.
// Row cached in registers: single global read + single global write.
// ---------------------------------------------------------------------------
__global__ __launch_bounds__(256) void softmax_rows(float* __restrict__ S)
{
    float* row = S + (size_t)blockIdx.x * SEQ;
    const int tid = threadIdx.x;
    __shared__ float red[8];

    float v[8];
    #pragma unroll
    for (int i = 0; i < 8; i++) v[i] = row[tid + i * 256];

    float m = v[0];
    #pragma unroll
    for (int i = 1; i < 8; i++) m = fmaxf(m, v[i]);
    #pragma unroll
    for (int o = 16; o; o >>= 1) m = fmaxf(m, __shfl_xor_sync(0xffffffffu, m, o));
    if ((tid & 31) == 0) red[tid >> 5] = m;
    __syncthreads();
    float mx = red[0];
    #pragma unroll
    for (int w = 1; w < 8; w++) mx = fmaxf(mx, red[w]);
    __syncthreads();

    float s = 0.f;
    #pragma unroll
    for (int i = 0; i < 8; i++) {
        v[i] = __expf(v[i] - mx);
        s += v[i];
    }
    #pragma unroll
    for (int o = 16; o; o >>= 1) s += __shfl_xor_sync(0xffffffffu, s, o);
    if ((tid & 31) == 0) red[tid >> 5] = s;
    __syncthreads();
    float tot = red[0];
    #pragma unroll
    for (int w = 1; w < 8; w++) tot += red[w];
    const float inv = 1.0f / tot;

    #pragma unroll
    for (int i = 0; i < 8; i++) row[tid + i * 256] = v[i] * inv;
}

// ---------------------------------------------------------------------------
extern "C" void kernel_launch(void* const* d_in, const int* in_sizes, int n_in,
                              void* d_out, int out_size)
{
    const float* x  = (const float*)d_in[0];
    const float* Wq = (const float*)d_in[1];
    const float* bq = (const float*)d_in[2];
    const float* Wk = (const float*)d_in[3];
    const float* bk = (const float*)d_in[4];
    const float* Wv = (const float*)d_in[5];
    const float* bv = (const float*)d_in[6];
    float* out = (float*)d_out;

    float *q, *k, *v, *s;
    cudaGetSymbolAddress((void**)&q, g_q);
    cudaGetSymbolAddress((void**)&k, g_k);
    cudaGetSymbolAddress((void**)&v, g_v);
    cudaGetSymbolAddress((void**)&s, g_s);

    const dim3 blk(256);

    // Q/K/V projections: [8192,1024] = x @ W + b
    const dim3 gQKV(DM / 128, (BATCH * SEQ) / 128, 1);
    gemm_nn<<<gQKV, blk>>>(x, Wq, bq, q, BATCH * SEQ, DM, DM, 0, 0, 0);
    gemm_nn<<<gQKV, blk>>>(x, Wk, bk, k, BATCH * SEQ, DM, DM, 0, 0, 0);
    gemm_nn<<<gQKV, blk>>>(x, Wv, bv, v, BATCH * SEQ, DM, DM, 0, 0, 0);

    // scores = scale * Q @ K^T  (per batch)
    const dim3 gS(SEQ / 128, SEQ / 128, BATCH);
    gemm_nt_scaled<<<gS, blk>>>(q, k, s, SEQ, SEQ, DM, 0.03125f,
                                (size_t)SEQ * DM, (size_t)SEQ * DM, (size_t)SEQ * SEQ);

    // softmax rows
    softmax_rows<<<BATCH * SEQ, blk>>>(s);

    // out = attn @ V  (per batch)
    const dim3 gO(DM / 128, SEQ / 128, BATCH);
    gemm_nn<<<gO, blk>>>(s, v, nullptr, out, SEQ, DM, SEQ,
                         (size_t)SEQ * SEQ, (size_t)SEQ * DM, (size_t)SEQ * DM);
}

// round 3
// speedup vs baseline: 2.5490x; 2.5490x over previous
#include <cuda_runtime.h>
#include <cuda_bf16.h>
#include <stdint.h>

#define BATCH 4
#define SEQ   2048
#define DM    1024
typedef __nv_bfloat16 bf16;

// ---------------- scratch (__device__ globals; no allocation) ----------------
__device__ bf16 g_xhi[(size_t)BATCH*SEQ*DM];
__device__ bf16 g_xlo[(size_t)BATCH*SEQ*DM];
__device__ bf16 g_wthi[(size_t)3*DM*DM];     // W^T hi (3 matrices)
__device__ bf16 g_wtlo[(size_t)3*DM*DM];
__device__ bf16 g_qhi[(size_t)BATCH*SEQ*DM];
__device__ bf16 g_qlo[(size_t)BATCH*SEQ*DM];
__device__ bf16 g_khi[(size_t)BATCH*SEQ*DM];
__device__ bf16 g_klo[(size_t)BATCH*SEQ*DM];
__device__ bf16 g_vhi[(size_t)BATCH*SEQ*DM];
__device__ bf16 g_vlo[(size_t)BATCH*SEQ*DM];
__device__ bf16 g_vthi[(size_t)BATCH*DM*SEQ];  // V^T
__device__ bf16 g_vtlo[(size_t)BATCH*DM*SEQ];
__device__ float g_s[(size_t)BATCH*SEQ*SEQ];   // scores fp32
__device__ bf16 g_ahi[(size_t)BATCH*SEQ*SEQ];  // attn probs hi/lo
__device__ bf16 g_alo[(size_t)BATCH*SEQ*SEQ];

// ---------------- helpers ----------------
__device__ __forceinline__ uint32_t s2u(const void* p) {
    uint32_t a;
    asm("{ .reg .u64 t; cvta.to.shared.u64 t, %1; cvt.u32.u64 %0, t; }" : "=r"(a) : "l"(p));
    return a;
}
__device__ __forceinline__ void ldsm4(uint32_t* r, uint32_t addr) {
    asm volatile("ldmatrix.sync.aligned.m8n8.x4.shared.b16 {%0,%1,%2,%3}, [%4];"
                 : "=r"(r[0]), "=r"(r[1]), "=r"(r[2]), "=r"(r[3]) : "r"(addr));
}
__device__ __forceinline__ void mma16816(float* d, const uint32_t* a, const uint32_t* b) {
    asm volatile(
        "mma.sync.aligned.m16n8k16.row.col.f32.bf16.bf16.f32 "
        "{%0,%1,%2,%3}, {%4,%5,%6,%7}, {%8,%9}, {%0,%1,%2,%3};"
        : "+f"(d[0]), "+f"(d[1]), "+f"(d[2]), "+f"(d[3])
        : "r"(a[0]), "r"(a[1]), "r"(a[2]), "r"(a[3]), "r"(b[0]), "r"(b[1]));
}

// ---------------- HMMA GEMM: C = scale*(A@B^T) [+bias], bf16x3 split ----------------
// A: hi/lo bf16 [M,K] row-major. B: hi/lo bf16 [N,K] row-major.
// Out: fp32 Cf OR split Chi/Clo [M,N] row-major. CTA tile 128x128, BK=64, 2 stages.
#define BK      64
#define STAGES  2
#define TILE_B  16384                    // 128 rows * 128B
#define STAGE_B (4 * TILE_B)             // Ahi, Alo, Bhi, Blo
#define GEMM_SMEM (STAGES * STAGE_B)     // 128 KB

__global__ __launch_bounds__(256, 1) void gemm_mma(
    const bf16* __restrict__ Ahi, const bf16* __restrict__ Alo,
    const bf16* __restrict__ Bhi, const bf16* __restrict__ Blo,
    const float* __restrict__ bias, float scale,
    float* __restrict__ Cf, bf16* __restrict__ Chi, bf16* __restrict__ Clo,
    int K, int N, size_t sA, size_t sB, size_t sC)
{
    extern __shared__ char smem[];
    const uint32_t sb = s2u(smem);
    const int tid = threadIdx.x;
    const int wid = tid >> 5, lane = tid & 31;
    const int wm = wid & 1, wn = wid >> 1;           // warp grid 2 (m) x 4 (n)
    const int m0 = blockIdx.y * 128, n0 = blockIdx.x * 128;
    const int NC = K / BK;

    const bf16* bAhi = Ahi + (size_t)blockIdx.z * sA + (size_t)m0 * K;
    const bf16* bAlo = Alo + (size_t)blockIdx.z * sA + (size_t)m0 * K;
    const bf16* bBhi = Bhi + (size_t)blockIdx.z * sB + (size_t)n0 * K;
    const bf16* bBlo = Blo + (size_t)blockIdx.z * sB + (size_t)n0 * K;

    auto load_chunk = [&](int c) {
        const uint32_t stg = sb + (uint32_t)(c & 1) * STAGE_B;
        const int k0 = c * BK;
        #pragma unroll
        for (int i = 0; i < 16; i++) {
            const int t = i >> 2;                       // 0..3: Ahi, Alo, Bhi, Blo
            const int sub = tid + (i & 3) * 256;        // 0..1023
            const int row = sub >> 3, col = sub & 7;    // 128 rows x 8 16B-cols
            const bf16* src = (t == 0 ? bAhi : t == 1 ? bAlo : t == 2 ? bBhi : bBlo)
                              + (size_t)row * K + k0 + col * 8;
            uint32_t off = (uint32_t)(row * 128 + col * 16);
            uint32_t dst = stg + (uint32_t)t * TILE_B + (off ^ ((off >> 3) & 0x70));
            asm volatile("cp.async.cg.shared.global [%0], [%1], 16;" :: "r"(dst), "l"(src) : "memory");
        }
        asm volatile("cp.async.commit_group;" ::: "memory");
    };

    // per-lane ldmatrix addressing (SW128 rows of 128B)
    const int rlane = (lane & 7) + ((lane >> 3) & 1) * 8;   // row within 16-row frag
    const uint32_t xlane = (uint32_t)((rlane & 7) * 16);    // swizzle XOR for this row
    const uint32_t kbl = (uint32_t)((lane >> 4) * 16);      // 16B col select (k half)
    uint32_t aoff[4], boff[2], kx[4];
    #pragma unroll
    for (int mf = 0; mf < 4; mf++) aoff[mf] = (uint32_t)((wm * 64 + mf * 16 + rlane) << 7);
    #pragma unroll
    for (int ng = 0; ng < 2; ng++) boff[ng] = (uint32_t)((wn * 32 + ng * 16 + rlane) << 7);
    #pragma unroll
    for (int ks = 0; ks < 4; ks++) kx[ks] = ((uint32_t)(ks * 32) + kbl) ^ xlane;

    float acc[4][4][4] = {};

    load_chunk(0);

    for (int c = 0; c < NC; ++c) {
        if (c + 1 < NC) {
            load_chunk(c + 1);
            asm volatile("cp.async.wait_group 1;" ::: "memory");
        } else {
            asm volatile("cp.async.wait_group 0;" ::: "memory");
        }
        __syncthreads();

        const uint32_t stg = sb + (uint32_t)(c & 1) * STAGE_B;
        const uint32_t sAh = stg, sAl = stg + TILE_B, sBh = stg + 2*TILE_B, sBl = stg + 3*TILE_B;

        #pragma unroll
        for (int ks = 0; ks < 4; ks++) {
            uint32_t ah[4][4], al[4][4], bh[4][2], bl[4][2];
            #pragma unroll
            for (int mf = 0; mf < 4; mf++) {
                ldsm4(ah[mf], sAh + aoff[mf] + kx[ks]);
                ldsm4(al[mf], sAl + aoff[mf] + kx[ks]);
            }
            #pragma unroll
            for (int ng = 0; ng < 2; ng++) {
                uint32_t t[4];
                ldsm4(t, sBh + boff[ng] + kx[ks]);
                bh[2*ng][0] = t[0]; bh[2*ng+1][0] = t[1];
                bh[2*ng][1] = t[2]; bh[2*ng+1][1] = t[3];
                ldsm4(t, sBl + boff[ng] + kx[ks]);
                bl[2*ng][0] = t[0]; bl[2*ng+1][0] = t[1];
                bl[2*ng][1] = t[2]; bl[2*ng+1][1] = t[3];
            }
            #pragma unroll
            for (int mf = 0; mf < 4; mf++)
                #pragma unroll
                for (int nf = 0; nf < 4; nf++) {
                    mma16816(acc[mf][nf], ah[mf], bh[nf]);
                    mma16816(acc[mf][nf], ah[mf], bl[nf]);
                    mma16816(acc[mf][nf], al[mf], bh[nf]);
                }
        }
        __syncthreads();
    }

    // ---------------- epilogue ----------------
    const size_t cb = (size_t)blockIdx.z * sC;
    #pragma unroll
    for (int mf = 0; mf < 4; mf++) {
        #pragma unroll
        for (int nf = 0; nf < 4; nf++) {
            const int m = m0 + wm * 64 + mf * 16 + (lane >> 2);
            const int n = n0 + wn * 32 + nf * 8 + 2 * (lane & 3);
            const float b0 = bias ? bias[n] : 0.f;
            const float b1 = bias ? bias[n + 1] : 0.f;
            float v00 = acc[mf][nf][0] * scale + b0;
            float v01 = acc[mf][nf][1] * scale + b1;
            float v10 = acc[mf][nf][2] * scale + b0;
            float v11 = acc[mf][nf][3] * scale + b1;
            if (Chi) {
                bf16 h00 = __float2bfloat16(v00), h01 = __float2bfloat16(v01);
                bf16 h10 = __float2bfloat16(v10), h11 = __float2bfloat16(v11);
                bf16 l00 = __float2bfloat16(v00 - __bfloat162float(h00));
                bf16 l01 = __float2bfloat16(v01 - __bfloat162float(h01));
                bf16 l10 = __float2bfloat16(v10 - __bfloat162float(h10));
                bf16 l11 = __float2bfloat16(v11 - __bfloat162float(h11));
                __nv_bfloat162 ph0 = {h00, h01}, ph1 = {h10, h11};
                __nv_bfloat162 pl0 = {l00, l01}, pl1 = {l10, l11};
                *reinterpret_cast<__nv_bfloat162*>(Chi + cb + (size_t)m * N + n)       = ph0;
                *reinterpret_cast<__nv_bfloat162*>(Chi + cb + (size_t)(m + 8) * N + n) = ph1;
                *reinterpret_cast<__nv_bfloat162*>(Clo + cb + (size_t)m * N + n)       = pl0;
                *reinterpret_cast<__nv_bfloat162*>(Clo + cb + (size_t)(m + 8) * N + n) = pl1;
            } else {
                float2 o0 = {v00, v01}, o1 = {v10, v11};
                *reinterpret_cast<float2*>(Cf + cb + (size_t)m * N + n)       = o0;
                *reinterpret_cast<float2*>(Cf + cb + (size_t)(m + 8) * N + n) = o1;
            }
        }
    }
}

// ---------------- aux kernels ----------------
__global__ __launch_bounds__(256) void split_f32(const float* __restrict__ in,
                                                 bf16* __restrict__ hi, bf16* __restrict__ lo, int n4)
{
    int i = blockIdx.x * 256 + threadIdx.x;
    if (i >= n4) return;
    float4 v = reinterpret_cast<const float4*>(in)[i];
    __align__(8) bf16 h[4];
    __align__(8) bf16 l[4];
    float f[4] = {v.x, v.y, v.z, v.w};
    #pragma unroll
    for (int j = 0; j < 4; j++) {
        h[j] = __float2bfloat16(f[j]);
        l[j] = __float2bfloat16(f[j] - __bfloat162float(h[j]));
    }
    reinterpret_cast<uint2*>(hi)[i] = *reinterpret_cast<uint2*>(h);
    reinterpret_cast<uint2*>(lo)[i] = *reinterpret_cast<uint2*>(l);
}

// W [K=DM, N=DM] fp32 -> wt hi/lo [N, K] bf16 (transposed), z selects Wq/Wk/Wv
__global__ void split_transpose_w(const float* __restrict__ Wq, const float* __restrict__ Wk,
                                  const float* __restrict__ Wv,
                                  bf16* __restrict__ hiO, bf16* __restrict__ loO)
{
    __shared__ float t[32][33];
    const float* W = blockIdx.z == 0 ? Wq : blockIdx.z == 1 ? Wk : Wv;
    bf16* hi = hiO + (size_t)blockIdx.z * DM * DM;
    bf16* lo = loO + (size_t)blockIdx.z * DM * DM;
    const int n0 = blockIdx.x * 32, k0 = blockIdx.y * 32;
    const int tx = threadIdx.x, ty = threadIdx.y;
    #pragma unroll
    for (int r = 0; r < 4; r++)
        t[ty + 8 * r][tx] = W[(size_t)(k0 + ty + 8 * r) * DM + n0 + tx];
    __syncthreads();
    #pragma unroll
    for (int r = 0; r < 4; r++) {
        float v = t[tx][ty + 8 * r];
        bf16 h = __float2bfloat16(v);
        bf16 l = __float2bfloat16(v - __bfloat162float(h));
        size_t o = (size_t)(n0 + ty + 8 * r) * DM + k0 + tx;
        hi[o] = h; lo[o] = l;
    }
}

// [B][SEQ][DM] -> [B][DM][SEQ] bf16 transpose
__global__ void transpose_bf16(const bf16* __restrict__ in, bf16* __restrict__ out)
{
    __shared__ bf16 t[32][33];
    const size_t ib = (size_t)blockIdx.z * SEQ * DM;
    const int s0 = blockIdx.y * 32, d0 = blockIdx.x * 32;
    const int tx = threadIdx.x, ty = threadIdx.y;
    #pragma unroll
    for (int r = 0; r < 4; r++)
        t[ty + 8 * r][tx] = in[ib + (size_t)(s0 + ty + 8 * r) * DM + d0 + tx];
    __syncthreads();
    #pragma unroll
    for (int r = 0; r < 4; r++)
        out[ib + (size_t)(d0 + ty + 8 * r) * SEQ + s0 + tx] = t[tx][ty + 8 * r];
}

// row softmax of fp32 scores -> bf16 hi/lo probabilities
__global__ __launch_bounds__(256) void softmax_split(const float* __restrict__ S,
                                                     bf16* __restrict__ Ph, bf16* __restrict__ Pl)
{
    const float* row = S + (size_t)blockIdx.x * SEQ;
    const int tid = threadIdx.x;
    __shared__ float red[8];

    float v[8];
    #pragma unroll
    for (int i = 0; i < 8; i++) v[i] = row[tid + i * 256];

    float m = v[0];
    #pragma unroll
    for (int i = 1; i < 8; i++) m = fmaxf(m, v[i]);
    #pragma unroll
    for (int o = 16; o; o >>= 1) m = fmaxf(m, __shfl_xor_sync(0xffffffffu, m, o));
    if ((tid & 31) == 0) red[tid >> 5] = m;
    __syncthreads();
    float mx = red[0];
    #pragma unroll
    for (int w = 1; w < 8; w++) mx = fmaxf(mx, red[w]);
    __syncthreads();

    float s = 0.f;
    #pragma unroll
    for (int i = 0; i < 8; i++) { v[i] = __expf(v[i] - mx); s += v[i]; }
    #pragma unroll
    for (int o = 16; o; o >>= 1) s += __shfl_xor_sync(0xffffffffu, s, o);
    if ((tid & 31) == 0) red[tid >> 5] = s;
    __syncthreads();
    float tot = red[0];
    #pragma unroll
    for (int w = 1; w < 8; w++) tot += red[w];
    const float inv = 1.0f / tot;

    const size_t ro = (size_t)blockIdx.x * SEQ;
    #pragma unroll
    for (int i = 0; i < 8; i++) {
        float p = v[i] * inv;
        bf16 h = __float2bfloat16(p);
        bf16 l = __float2bfloat16(p - __bfloat162float(h));
        Ph[ro + tid + i * 256] = h;
        Pl[ro + tid + i * 256] = l;
    }
}

// ---------------- launcher ----------------
extern "C" void kernel_launch(void* const* d_in, const int* in_sizes, int n_in,
                              void* d_out, int out_size)
{
    const float* x  = (const float*)d_in[0];
    const float* Wq = (const float*)d_in[1];
    const float* bq = (const float*)d_in[2];
    const float* Wk = (const float*)d_in[3];
    const float* bk = (const float*)d_in[4];
    const float* Wv = (const float*)d_in[5];
    const float* bv = (const float*)d_in[6];
    float* out = (float*)d_out;

    bf16 *xhi, *xlo, *wthi, *wtlo, *qhi, *qlo, *khi, *klo, *vhi, *vlo, *vthi, *vtlo, *ahi, *alo;
    float* s;
    cudaGetSymbolAddress((void**)&xhi, g_xhi);   cudaGetSymbolAddress((void**)&xlo, g_xlo);
    cudaGetSymbolAddress((void**)&wthi, g_wthi); cudaGetSymbolAddress((void**)&wtlo, g_wtlo);
    cudaGetSymbolAddress((void**)&qhi, g_qhi);   cudaGetSymbolAddress((void**)&qlo, g_qlo);
    cudaGetSymbolAddress((void**)&khi, g_khi);   cudaGetSymbolAddress((void**)&klo, g_klo);
    cudaGetSymbolAddress((void**)&vhi, g_vhi);   cudaGetSymbolAddress((void**)&vlo, g_vlo);
    cudaGetSymbolAddress((void**)&vthi, g_vthi); cudaGetSymbolAddress((void**)&vtlo, g_vtlo);
    cudaGetSymbolAddress((void**)&ahi, g_ahi);   cudaGetSymbolAddress((void**)&alo, g_alo);
    cudaGetSymbolAddress((void**)&s, g_s);

    cudaFuncSetAttribute(gemm_mma, cudaFuncAttributeMaxDynamicSharedMemorySize, GEMM_SMEM);

    const int M = BATCH * SEQ;

    // 1. split x into bf16 hi/lo
    split_f32<<<(M * DM / 4 + 255) / 256, 256>>>(x, xhi, xlo, M * DM / 4);
    // 2. split + transpose weights
    split_transpose_w<<<dim3(DM / 32, DM / 32, 3), dim3(32, 8)>>>(Wq, Wk, Wv, wthi, wtlo);

    // 3. QKV projections (split bf16 outputs, fused bias)
    const dim3 gP(DM / 128, M / 128, 1);
    gemm_mma<<<gP, 256, GEMM_SMEM>>>(xhi, xlo, wthi,                    wtlo,                    bq, 1.f,
                                     nullptr, qhi, qlo, DM, DM, 0, 0, 0);
    gemm_mma<<<gP, 256, GEMM_SMEM>>>(xhi, xlo, wthi + (size_t)DM*DM,    wtlo + (size_t)DM*DM,    bk, 1.f,
                                     nullptr, khi, klo, DM, DM, 0, 0, 0);
    gemm_mma<<<gP, 256, GEMM_SMEM>>>(xhi, xlo, wthi + (size_t)2*DM*DM,  wtlo + (size_t)2*DM*DM,  bv, 1.f,
                                     nullptr, vhi, vlo, DM, DM, 0, 0, 0);

    // 4. V^T for the AV GEMM
    transpose_bf16<<<dim3(DM / 32, SEQ / 32, BATCH), dim3(32, 8)>>>(vhi, vthi);
    transpose_bf16<<<dim3(DM / 32, SEQ / 32, BATCH), dim3(32, 8)>>>(vlo, vtlo);

    // 5. scores = scale * Q @ K^T  (fp32 out)
    gemm_mma<<<dim3(SEQ / 128, SEQ / 128, BATCH), 256, GEMM_SMEM>>>(
        qhi, qlo, khi, klo, nullptr, 0.03125f,
        s, nullptr, nullptr, DM, SEQ,
        (size_t)SEQ * DM, (size_t)SEQ * DM, (size_t)SEQ * SEQ);

    // 6. softmax -> split attn probs
    softmax_split<<<BATCH * SEQ, 256>>>(s, ahi, alo);

    // 7. out = attn @ V  (fp32 out)
    gemm_mma<<<dim3(DM / 128, SEQ / 128, BATCH), 256, GEMM_SMEM>>>(
        ahi, alo, vthi, vtlo, nullptr, 1.f,
        out, nullptr, nullptr, SEQ, DM,
        (size_t)SEQ * SEQ, (size_t)DM * SEQ, (size_t)SEQ * DM);
}

// round 4
// speedup vs baseline: 2.7040x; 1.0608x over previous
#include <cuda_runtime.h>
#include <cuda_bf16.h>
#include <stdint.h>

#define BATCH 4
#define SEQ   2048
#define DM    1024
typedef __nv_bfloat16 bf16;

// ---------------- scratch (__device__ globals; no allocation) ----------------
__device__ bf16 g_xhi[(size_t)BATCH*SEQ*DM];
__device__ bf16 g_xlo[(size_t)BATCH*SEQ*DM];
__device__ bf16 g_wthi[(size_t)3*DM*DM];       // W^T hi: [3*DM rows][DM]
__device__ bf16 g_wtlo[(size_t)3*DM*DM];
__device__ float g_bias[3*DM];
__device__ bf16 g_qkvhi[(size_t)BATCH*SEQ*3*DM]; // [B*SEQ][3*DM]: q|k|v
__device__ bf16 g_qkvlo[(size_t)BATCH*SEQ*3*DM];
__device__ bf16 g_vthi[(size_t)BATCH*DM*SEQ];    // V^T
__device__ bf16 g_vtlo[(size_t)BATCH*DM*SEQ];
__device__ float g_s[(size_t)BATCH*SEQ*SEQ];     // scores fp32
__device__ bf16 g_ahi[(size_t)BATCH*SEQ*SEQ];    // attn probs hi/lo
__device__ bf16 g_alo[(size_t)BATCH*SEQ*SEQ];

// ---------------- helpers ----------------
__device__ __forceinline__ uint32_t s2u(const void* p) {
    uint32_t a;
    asm("{ .reg .u64 t; cvta.to.shared.u64 t, %1; cvt.u32.u64 %0, t; }" : "=r"(a) : "l"(p));
    return a;
}
__device__ __forceinline__ void ldsm4(uint32_t* r, uint32_t addr) {
    asm volatile("ldmatrix.sync.aligned.m8n8.x4.shared.b16 {%0,%1,%2,%3}, [%4];"
                 : "=r"(r[0]), "=r"(r[1]), "=r"(r[2]), "=r"(r[3]) : "r"(addr));
}
__device__ __forceinline__ void mma16816(float* d, const uint32_t* a, const uint32_t* b) {
    asm volatile(
        "mma.sync.aligned.m16n8k16.row.col.f32.bf16.bf16.f32 "
        "{%0,%1,%2,%3}, {%4,%5,%6,%7}, {%8,%9}, {%0,%1,%2,%3};"
        : "+f"(d[0]), "+f"(d[1]), "+f"(d[2]), "+f"(d[3])
        : "r"(a[0]), "r"(a[1]), "r"(a[2]), "r"(a[3]), "r"(b[0]), "r"(b[1]));
}

// ---------------- HMMA GEMM: C = scale*(A@B^T) [+bias], bf16x3 split ----------------
// A: hi/lo bf16 [M,K] rows stride lda. B: hi/lo bf16 [N,K] rows stride ldb.
// Out fp32 Cf OR split Chi/Clo, rows stride ldc. CTA 128x128, BK=64, 3 stages, 512 thr.
#define BK      64
#define STAGES  3
#define TILE_B  16384                    // 128 rows * 128B
#define STAGE_B (4 * TILE_B)             // Ahi, Alo, Bhi, Blo
#define GEMM_SMEM (STAGES * STAGE_B)     // 192 KB

__global__ __launch_bounds__(512, 1) void gemm_mma(
    const bf16* __restrict__ Ahi, const bf16* __restrict__ Alo,
    const bf16* __restrict__ Bhi, const bf16* __restrict__ Blo,
    const float* __restrict__ bias, float scale,
    float* __restrict__ Cf, bf16* __restrict__ Chi, bf16* __restrict__ Clo,
    int K, int lda, int ldb, int ldc,
    size_t sA, size_t sB, size_t sC)
{
    extern __shared__ char smem[];
    const uint32_t sb = s2u(smem);
    const int tid = threadIdx.x;
    const int wid = tid >> 5, lane = tid & 31;
    const int wm = wid & 3, wn = wid >> 2;           // warp grid 4 (m) x 4 (n)
    const int m0 = blockIdx.y * 128, n0 = blockIdx.x * 128;
    const int NC = K / BK;

    const bf16* bAhi = Ahi + (size_t)blockIdx.z * sA + (size_t)m0 * lda;
    const bf16* bAlo = Alo + (size_t)blockIdx.z * sA + (size_t)m0 * lda;
    const bf16* bBhi = Bhi + (size_t)blockIdx.z * sB + (size_t)n0 * ldb;
    const bf16* bBlo = Blo + (size_t)blockIdx.z * sB + (size_t)n0 * ldb;

    auto load_chunk = [&](int c) {
        const uint32_t stg = sb + (uint32_t)(c % STAGES) * STAGE_B;
        const int k0 = c * BK;
        #pragma unroll
        for (int i = 0; i < 8; i++) {
            const int t = i >> 1;                       // 0..3: Ahi, Alo, Bhi, Blo
            const int sub = tid + (i & 1) * 512;        // 0..1023
            const int row = sub >> 3, col = sub & 7;    // 128 rows x 8 16B-cols
            const int ld = (t < 2) ? lda : ldb;
            const bf16* src = (t == 0 ? bAhi : t == 1 ? bAlo : t == 2 ? bBhi : bBlo)
                              + (size_t)row * ld + k0 + col * 8;
            uint32_t off = (uint32_t)(row * 128 + col * 16);
            uint32_t dst = stg + (uint32_t)t * TILE_B + (off ^ ((off >> 3) & 0x70));
            asm volatile("cp.async.cg.shared.global [%0], [%1], 16;" :: "r"(dst), "l"(src) : "memory");
        }
        asm volatile("cp.async.commit_group;" ::: "memory");
    };

    // per-lane ldmatrix addressing (SW128 rows of 128B)
    const int rlane = (lane & 7) + ((lane >> 3) & 1) * 8;   // row within 16-row frag
    const uint32_t xlane = (uint32_t)((rlane & 7) * 16);    // swizzle XOR for this row
    const uint32_t kbl = (uint32_t)((lane >> 4) * 16);      // 16B col select (k half)
    uint32_t aoff[2], boff[2], kx[4];
    #pragma unroll
    for (int mf = 0; mf < 2; mf++) aoff[mf] = (uint32_t)((wm * 32 + mf * 16 + rlane) << 7);
    #pragma unroll
    for (int ng = 0; ng < 2; ng++) boff[ng] = (uint32_t)((wn * 32 + ng * 16 + rlane) << 7);
    #pragma unroll
    for (int ks = 0; ks < 4; ks++) kx[ks] = ((uint32_t)(ks * 32) + kbl) ^ xlane;

    float acc[2][4][4] = {};

    load_chunk(0);
    if (NC > 1) load_chunk(1);

    for (int c = 0; c < NC; ++c) {
        if (c + 1 < NC) asm volatile("cp.async.wait_group 1;" ::: "memory");
        else            asm volatile("cp.async.wait_group 0;" ::: "memory");
        __syncthreads();                       // chunk c visible; stage (c+2)%3 free
        if (c + 2 < NC) load_chunk(c + 2);

        const uint32_t stg = sb + (uint32_t)(c % STAGES) * STAGE_B;
        const uint32_t sAh = stg, sAl = stg + TILE_B, sBh = stg + 2*TILE_B, sBl = stg + 3*TILE_B;

        #pragma unroll
        for (int ks = 0; ks < 4; ks++) {
            uint32_t ah[2][4], al[2][4], bh[4][2], bl[4][2];
            #pragma unroll
            for (int mf = 0; mf < 2; mf++) {
                ldsm4(ah[mf], sAh + aoff[mf] + kx[ks]);
                ldsm4(al[mf], sAl + aoff[mf] + kx[ks]);
            }
            #pragma unroll
            for (int ng = 0; ng < 2; ng++) {
                uint32_t t[4];
                ldsm4(t, sBh + boff[ng] + kx[ks]);
                bh[2*ng][0] = t[0]; bh[2*ng+1][0] = t[1];
                bh[2*ng][1] = t[2]; bh[2*ng+1][1] = t[3];
                ldsm4(t, sBl + boff[ng] + kx[ks]);
                bl[2*ng][0] = t[0]; bl[2*ng+1][0] = t[1];
                bl[2*ng][1] = t[2]; bl[2*ng+1][1] = t[3];
            }
            #pragma unroll
            for (int mf = 0; mf < 2; mf++)
                #pragma unroll
                for (int nf = 0; nf < 4; nf++) {
                    mma16816(acc[mf][nf], ah[mf], bh[nf]);
                    mma16816(acc[mf][nf], ah[mf], bl[nf]);
                    mma16816(acc[mf][nf], al[mf], bh[nf]);
                }
        }
    }

    // ---------------- epilogue ----------------
    const size_t cb = (size_t)blockIdx.z * sC;
    #pragma unroll
    for (int mf = 0; mf < 2; mf++) {
        #pragma unroll
        for (int nf = 0; nf < 4; nf++) {
            const int m = m0 + wm * 32 + mf * 16 + (lane >> 2);
            const int n = n0 + wn * 32 + nf * 8 + 2 * (lane & 3);
            const float b0 = bias ? bias[n] : 0.f;
            const float b1 = bias ? bias[n + 1] : 0.f;
            float v00 = acc[mf][nf][0] * scale + b0;
            float v01 = acc[mf][nf][1] * scale + b1;
            float v10 = acc[mf][nf][2] * scale + b0;
            float v11 = acc[mf][nf][3] * scale + b1;
            if (Chi) {
                bf16 h00 = __float2bfloat16(v00), h01 = __float2bfloat16(v01);
                bf16 h10 = __float2bfloat16(v10), h11 = __float2bfloat16(v11);
                bf16 l00 = __float2bfloat16(v00 - __bfloat162float(h00));
                bf16 l01 = __float2bfloat16(v01 - __bfloat162float(h01));
                bf16 l10 = __float2bfloat16(v10 - __bfloat162float(h10));
                bf16 l11 = __float2bfloat16(v11 - __bfloat162float(h11));
                __nv_bfloat162 ph0 = {h00, h01}, ph1 = {h10, h11};
                __nv_bfloat162 pl0 = {l00, l01}, pl1 = {l10, l11};
                *reinterpret_cast<__nv_bfloat162*>(Chi + cb + (size_t)m * ldc + n)       = ph0;
                *reinterpret_cast<__nv_bfloat162*>(Chi + cb + (size_t)(m + 8) * ldc + n) = ph1;
                *reinterpret_cast<__nv_bfloat162*>(Clo + cb + (size_t)m * ldc + n)       = pl0;
                *reinterpret_cast<__nv_bfloat162*>(Clo + cb + (size_t)(m + 8) * ldc + n) = pl1;
            } else {
                float2 o0 = {v00, v01}, o1 = {v10, v11};
                *reinterpret_cast<float2*>(Cf + cb + (size_t)m * ldc + n)       = o0;
                *reinterpret_cast<float2*>(Cf + cb + (size_t)(m + 8) * ldc + n) = o1;
            }
        }
    }
}

// ---------------- aux kernels ----------------
__global__ __launch_bounds__(256) void split_f32(const float* __restrict__ in,
                                                 bf16* __restrict__ hi, bf16* __restrict__ lo, int n4)
{
    int i = blockIdx.x * 256 + threadIdx.x;
    if (i >= n4) return;
    float4 v = reinterpret_cast<const float4*>(in)[i];
    __align__(8) bf16 h[4];
    __align__(8) bf16 l[4];
    float f[4] = {v.x, v.y, v.z, v.w};
    #pragma unroll
    for (int j = 0; j < 4; j++) {
        h[j] = __float2bfloat16(f[j]);
        l[j] = __float2bfloat16(f[j] - __bfloat162float(h[j]));
    }
    reinterpret_cast<uint2*>(hi)[i] = *reinterpret_cast<uint2*>(h);
    reinterpret_cast<uint2*>(lo)[i] = *reinterpret_cast<uint2*>(l);
}

__global__ void concat_bias(const float* a, const float* b, const float* c, float* o)
{
    int i = blockIdx.x * 256 + threadIdx.x;
    if (i < DM)            o[i] = a[i];
    else if (i < 2 * DM)   o[i] = b[i - DM];
    else if (i < 3 * DM)   o[i] = c[i - 2 * DM];
}

// W [K=DM, N=DM] fp32 -> wt hi/lo [N, K] bf16 (transposed), z selects Wq/Wk/Wv
__global__ void split_transpose_w(const float* __restrict__ Wq, const float* __restrict__ Wk,
                                  const float* __restrict__ Wv,
                                  bf16* __restrict__ hiO, bf16* __restrict__ loO)
{
    __shared__ float t[32][33];
    const float* W = blockIdx.z == 0 ? Wq : blockIdx.z == 1 ? Wk : Wv;
    bf16* hi = hiO + (size_t)blockIdx.z * DM * DM;
    bf16* lo = loO + (size_t)blockIdx.z * DM * DM;
    const int n0 = blockIdx.x * 32, k0 = blockIdx.y * 32;
    const int tx = threadIdx.x, ty = threadIdx.y;
    #pragma unroll
    for (int r = 0; r < 4; r++)
        t[ty + 8 * r][tx] = W[(size_t)(k0 + ty + 8 * r) * DM + n0 + tx];
    __syncthreads();
    #pragma unroll
    for (int r = 0; r < 4; r++) {
        float v = t[tx][ty + 8 * r];
        bf16 h = __float2bfloat16(v);
        bf16 l = __float2bfloat16(v - __bfloat162float(h));
        size_t o = (size_t)(n0 + ty + 8 * r) * DM + k0 + tx;
        hi[o] = h; lo[o] = l;
    }
}

// V slice of [B][SEQ][3*DM] -> [B][DM][SEQ] bf16 transpose (input rows stride ldin)
__global__ void transpose_bf16(const bf16* __restrict__ in, bf16* __restrict__ out, int ldin)
{
    __shared__ bf16 t[32][33];
    const size_t ib = (size_t)blockIdx.z * SEQ * ldin;
    const size_t ob = (size_t)blockIdx.z * DM * SEQ;
    const int s0 = blockIdx.y * 32, d0 = blockIdx.x * 32;
    const int tx = threadIdx.x, ty = threadIdx.y;
    #pragma unroll
    for (int r = 0; r < 4; r++)
        t[ty + 8 * r][tx] = in[ib + (size_t)(s0 + ty + 8 * r) * ldin + d0 + tx];
    __syncthreads();
    #pragma unroll
    for (int r = 0; r < 4; r++)
        out[ob + (size_t)(d0 + ty + 8 * r) * SEQ + s0 + tx] = t[tx][ty + 8 * r];
}

// row softmax of fp32 scores -> bf16 hi/lo probabilities
__global__ __launch_bounds__(256) void softmax_split(const float* __restrict__ S,
                                                     bf16* __restrict__ Ph, bf16* __restrict__ Pl)
{
    const float* row = S + (size_t)blockIdx.x * SEQ;
    const int tid = threadIdx.x;
    __shared__ float red[8];

    float v[8];
    #pragma unroll
    for (int i = 0; i < 8; i++) v[i] = row[tid + i * 256];

    float m = v[0];
    #pragma unroll
    for (int i = 1; i < 8; i++) m = fmaxf(m, v[i]);
    #pragma unroll
    for (int o = 16; o; o >>= 1) m = fmaxf(m, __shfl_xor_sync(0xffffffffu, m, o));
    if ((tid & 31) == 0) red[tid >> 5] = m;
    __syncthreads();
    float mx = red[0];
    #pragma unroll
    for (int w = 1; w < 8; w++) mx = fmaxf(mx, red[w]);
    __syncthreads();

    float s = 0.f;
    #pragma unroll
    for (int i = 0; i < 8; i++) { v[i] = __expf(v[i] - mx); s += v[i]; }
    #pragma unroll
    for (int o = 16; o; o >>= 1) s += __shfl_xor_sync(0xffffffffu, s, o);
    if ((tid & 31) == 0) red[tid >> 5] = s;
    __syncthreads();
    float tot = red[0];
    #pragma unroll
    for (int w = 1; w < 8; w++) tot += red[w];
    const float inv = 1.0f / tot;

    const size_t ro = (size_t)blockIdx.x * SEQ;
    #pragma unroll
    for (int i = 0; i < 8; i++) {
        float p = v[i] * inv;
        bf16 h = __float2bfloat16(p);
        bf16 l = __float2bfloat16(p - __bfloat162float(h));
        Ph[ro + tid + i * 256] = h;
        Pl[ro + tid + i * 256] = l;
    }
}

// ---------------- launcher ----------------
extern "C" void kernel_launch(void* const* d_in, const int* in_sizes, int n_in,
                              void* d_out, int out_size)
{
    const float* x  = (const float*)d_in[0];
    const float* Wq = (const float*)d_in[1];
    const float* bq = (const float*)d_in[2];
    const float* Wk = (const float*)d_in[3];
    const float* bk = (const float*)d_in[4];
    const float* Wv = (const float*)d_in[5];
    const float* bv = (const float*)d_in[6];
    float* out = (float*)d_out;

    bf16 *xhi, *xlo, *wthi, *wtlo, *qkvhi, *qkvlo, *vthi, *vtlo, *ahi, *alo;
    float *s, *bias;
    cudaGetSymbolAddress((void**)&xhi, g_xhi);     cudaGetSymbolAddress((void**)&xlo, g_xlo);
    cudaGetSymbolAddress((void**)&wthi, g_wthi);   cudaGetSymbolAddress((void**)&wtlo, g_wtlo);
    cudaGetSymbolAddress((void**)&qkvhi, g_qkvhi); cudaGetSymbolAddress((void**)&qkvlo, g_qkvlo);
    cudaGetSymbolAddress((void**)&vthi, g_vthi);   cudaGetSymbolAddress((void**)&vtlo, g_vtlo);
    cudaGetSymbolAddress((void**)&ahi, g_ahi);     cudaGetSymbolAddress((void**)&alo, g_alo);
    cudaGetSymbolAddress((void**)&s, g_s);         cudaGetSymbolAddress((void**)&bias, g_bias);

    cudaFuncSetAttribute(gemm_mma, cudaFuncAttributeMaxDynamicSharedMemorySize, GEMM_SMEM);

    const int M = BATCH * SEQ;

    // 1. split x; split+transpose W; concat bias
    split_f32<<<(M * DM / 4 + 255) / 256, 256>>>(x, xhi, xlo, M * DM / 4);
    split_transpose_w<<<dim3(DM / 32, DM / 32, 3), dim3(32, 8)>>>(Wq, Wk, Wv, wthi, wtlo);
    concat_bias<<<(3 * DM + 255) / 256, 256>>>(bq, bk, bv, bias);

    // 2. fused QKV projection: [8192, 3072] = x @ [Wq|Wk|Wv] + bias
    gemm_mma<<<dim3(3 * DM / 128, M / 128, 1), 512, GEMM_SMEM>>>(
        xhi, xlo, wthi, wtlo, bias, 1.f,
        nullptr, qkvhi, qkvlo, DM, DM, DM, 3 * DM, 0, 0, 0);

    // 3. V^T for the AV GEMM (V = qkv columns [2048, 3072))
    transpose_bf16<<<dim3(DM / 32, SEQ / 32, BATCH), dim3(32, 8)>>>(qkvhi + 2 * DM, vthi, 3 * DM);
    transpose_bf16<<<dim3(DM / 32, SEQ / 32, BATCH), dim3(32, 8)>>>(qkvlo + 2 * DM, vtlo, 3 * DM);

    // 4. scores = scale * Q @ K^T (fp32 out)
    gemm_mma<<<dim3(SEQ / 128, SEQ / 128, BATCH), 512, GEMM_SMEM>>>(
        qkvhi, qkvlo, qkvhi + DM, qkvlo + DM, nullptr, 0.03125f,
        s, nullptr, nullptr, DM, 3 * DM, 3 * DM, SEQ,
        (size_t)SEQ * 3 * DM, (size_t)SEQ * 3 * DM, (size_t)SEQ * SEQ);

    // 5. softmax -> split attn probs
    softmax_split<<<BATCH * SEQ, 256>>>(s, ahi, alo);

    // 6. out = attn @ V (fp32 out)
    gemm_mma<<<dim3(DM / 128, SEQ / 128, BATCH), 512, GEMM_SMEM>>>(
        ahi, alo, vthi, vtlo, nullptr, 1.f,
        out, nullptr, nullptr, SEQ, SEQ, SEQ, DM,
        (size_t)SEQ * SEQ, (size_t)DM * SEQ, (size_t)SEQ * DM);
}

// round 5
// speedup vs baseline: 3.6729x; 1.3583x over previous
#include <cuda_runtime.h>
#include <cuda_fp16.h>
#include <stdint.h>

#define BATCH 4
#define SEQ   2048
#define DM    1024
typedef __half fp16;

// ---------------- scratch (__device__ globals; no allocation) ----------------
__device__ fp16 g_xhi[(size_t)BATCH*SEQ*DM];
__device__ fp16 g_xlo[(size_t)BATCH*SEQ*DM];
__device__ fp16 g_wt[(size_t)3*DM*DM];            // W^T single fp16: [3*DM][DM]
__device__ float g_bias[3*DM];
__device__ fp16 g_qkvhi[(size_t)BATCH*SEQ*3*DM];  // [B*S][3DM]: q_hi | k | v
__device__ fp16 g_qlo[(size_t)BATCH*SEQ*DM];      // q_lo only
__device__ fp16 g_vt[(size_t)BATCH*DM*SEQ];       // V^T single
__device__ float g_s[(size_t)BATCH*SEQ*SEQ];      // scores fp32
__device__ fp16 g_phi[(size_t)BATCH*SEQ*SEQ];     // attn probs hi/lo
__device__ fp16 g_plo[(size_t)BATCH*SEQ*SEQ];

// ---------------- helpers ----------------
__device__ __forceinline__ uint32_t s2u(const void* p) {
    uint32_t a;
    asm("{ .reg .u64 t; cvta.to.shared.u64 t, %1; cvt.u32.u64 %0, t; }" : "=r"(a) : "l"(p));
    return a;
}
__device__ __forceinline__ void ldsm4(uint32_t* r, uint32_t addr) {
    asm volatile("ldmatrix.sync.aligned.m8n8.x4.shared.b16 {%0,%1,%2,%3}, [%4];"
                 : "=r"(r[0]), "=r"(r[1]), "=r"(r[2]), "=r"(r[3]) : "r"(addr));
}
__device__ __forceinline__ void mma16816(float* d, const uint32_t* a, const uint32_t* b) {
    asm volatile(
        "mma.sync.aligned.m16n8k16.row.col.f32.f16.f16.f32 "
        "{%0,%1,%2,%3}, {%4,%5,%6,%7}, {%8,%9}, {%0,%1,%2,%3};"
        : "+f"(d[0]), "+f"(d[1]), "+f"(d[2]), "+f"(d[3])
        : "r"(a[0]), "r"(a[1]), "r"(a[2]), "r"(a[3]), "r"(b[0]), "r"(b[1]));
}

// ---------------- HMMA GEMM: C = scale*(A@B^T) [+bias], fp16 2-product ----------------
// A split hi/lo [M,K] (strides lda/ldalo); B single fp16 [N,K] (stride ldb).
// Out: fp32 Cf (stride ldc) OR fp16 Chi (+ optional lo for n0 < splitn, stride ldclo).
// CTA 128x128, BK=64, 3 stages, 512 threads, warp tile 32x32.
#define BK      64
#define STAGES  3
#define TILE_B  16384                    // 128 rows * 128B
#define STAGE_B (3 * TILE_B)             // Ahi, Alo, B
#define GEMM_SMEM (STAGES * STAGE_B)     // 144 KB

__global__ __launch_bounds__(512, 1) void gemm2p(
    const fp16* __restrict__ Ahi, const fp16* __restrict__ Alo,
    const fp16* __restrict__ B,
    const float* __restrict__ bias, float scale,
    float* __restrict__ Cf, fp16* __restrict__ Chi, fp16* __restrict__ Clo,
    int K, int lda, int ldalo, int ldb, int ldc, int ldclo, int splitn,
    size_t sA, size_t sAlo, size_t sB, size_t sC)
{
    extern __shared__ char smem[];
    const uint32_t sb = s2u(smem);
    const int tid = threadIdx.x;
    const int wid = tid >> 5, lane = tid & 31;
    const int wm = wid & 3, wn = wid >> 2;           // warp grid 4 (m) x 4 (n)
    const int m0 = blockIdx.y * 128, n0 = blockIdx.x * 128;
    const int NC = K / BK;

    const fp16* bAhi = Ahi + (size_t)blockIdx.z * sA   + (size_t)m0 * lda;
    const fp16* bAlo = Alo + (size_t)blockIdx.z * sAlo + (size_t)m0 * ldalo;
    const fp16* bB   = B   + (size_t)blockIdx.z * sB   + (size_t)n0 * ldb;

    auto load_chunk = [&](int c) {
        const uint32_t stg = sb + (uint32_t)(c % STAGES) * STAGE_B;
        const int k0 = c * BK;
        #pragma unroll
        for (int i = 0; i < 6; i++) {
            const int t = i >> 1;                       // 0: Ahi, 1: Alo, 2: B
            const int sub = tid + (i & 1) * 512;        // 0..1023
            const int row = sub >> 3, col = sub & 7;    // 128 rows x 8 16B-cols
            const int ld = (t == 0) ? lda : (t == 1) ? ldalo : ldb;
            const fp16* src = (t == 0 ? bAhi : t == 1 ? bAlo : bB)
                              + (size_t)row * ld + k0 + col * 8;
            uint32_t off = (uint32_t)(row * 128 + col * 16);
            uint32_t dst = stg + (uint32_t)t * TILE_B + (off ^ ((off >> 3) & 0x70));
            asm volatile("cp.async.cg.shared.global [%0], [%1], 16;" :: "r"(dst), "l"(src) : "memory");
        }
        asm volatile("cp.async.commit_group;" ::: "memory");
    };

    // per-lane ldmatrix addressing (SW128 rows of 128B)
    const int rlane = (lane & 7) + ((lane >> 3) & 1) * 8;
    const uint32_t xlane = (uint32_t)((rlane & 7) * 16);
    const uint32_t kbl = (uint32_t)((lane >> 4) * 16);
    uint32_t aoff[2], boff[2], kx[4];
    #pragma unroll
    for (int mf = 0; mf < 2; mf++) aoff[mf] = (uint32_t)((wm * 32 + mf * 16 + rlane) << 7);
    #pragma unroll
    for (int ng = 0; ng < 2; ng++) boff[ng] = (uint32_t)((wn * 32 + ng * 16 + rlane) << 7);
    #pragma unroll
    for (int ks = 0; ks < 4; ks++) kx[ks] = ((uint32_t)(ks * 32) + kbl) ^ xlane;

    float acc[2][4][4] = {};

    load_chunk(0);
    if (NC > 1) load_chunk(1);

    for (int c = 0; c < NC; ++c) {
        if (c + 1 < NC) asm volatile("cp.async.wait_group 1;" ::: "memory");
        else            asm volatile("cp.async.wait_group 0;" ::: "memory");
        __syncthreads();                       // chunk c visible; stage (c+2)%3 free
        if (c + 2 < NC) load_chunk(c + 2);

        const uint32_t stg = sb + (uint32_t)(c % STAGES) * STAGE_B;
        const uint32_t sAh = stg, sAl = stg + TILE_B, sB_ = stg + 2 * TILE_B;

        #pragma unroll
        for (int ks = 0; ks < 4; ks++) {
            uint32_t ah[2][4], al[2][4], bf[4][2];
            #pragma unroll
            for (int mf = 0; mf < 2; mf++) {
                ldsm4(ah[mf], sAh + aoff[mf] + kx[ks]);
                ldsm4(al[mf], sAl + aoff[mf] + kx[ks]);
            }
            #pragma unroll
            for (int ng = 0; ng < 2; ng++) {
                uint32_t t[4];
                ldsm4(t, sB_ + boff[ng] + kx[ks]);
                bf[2*ng][0] = t[0]; bf[2*ng+1][0] = t[1];
                bf[2*ng][1] = t[2]; bf[2*ng+1][1] = t[3];
            }
            #pragma unroll
            for (int mf = 0; mf < 2; mf++)
                #pragma unroll
                for (int nf = 0; nf < 4; nf++) {
                    mma16816(acc[mf][nf], ah[mf], bf[nf]);
                    mma16816(acc[mf][nf], al[mf], bf[nf]);
                }
        }
    }

    // ---------------- epilogue ----------------
    const bool do_split = Clo && (n0 < splitn);
    const size_t cb = (size_t)blockIdx.z * sC;
    #pragma unroll
    for (int mf = 0; mf < 2; mf++) {
        #pragma unroll
        for (int nf = 0; nf < 4; nf++) {
            const int m = m0 + wm * 32 + mf * 16 + (lane >> 2);
            const int n = n0 + wn * 32 + nf * 8 + 2 * (lane & 3);
            const float b0 = bias ? bias[n] : 0.f;
            const float b1 = bias ? bias[n + 1] : 0.f;
            float v00 = acc[mf][nf][0] * scale + b0;
            float v01 = acc[mf][nf][1] * scale + b1;
            float v10 = acc[mf][nf][2] * scale + b0;
            float v11 = acc[mf][nf][3] * scale + b1;
            if (Cf) {
                float2 o0 = {v00, v01}, o1 = {v10, v11};
                *reinterpret_cast<float2*>(Cf + cb + (size_t)m * ldc + n)       = o0;
                *reinterpret_cast<float2*>(Cf + cb + (size_t)(m + 8) * ldc + n) = o1;
            } else {
                fp16 h00 = __float2half(v00), h01 = __float2half(v01);
                fp16 h10 = __float2half(v10), h11 = __float2half(v11);
                __half2 ph0 = {h00, h01}, ph1 = {h10, h11};
                *reinterpret_cast<__half2*>(Chi + cb + (size_t)m * ldc + n)       = ph0;
                *reinterpret_cast<__half2*>(Chi + cb + (size_t)(m + 8) * ldc + n) = ph1;
                if (do_split) {
                    __half2 pl0 = {__float2half(v00 - __half2float(h00)),
                                   __float2half(v01 - __half2float(h01))};
                    __half2 pl1 = {__float2half(v10 - __half2float(h10)),
                                   __float2half(v11 - __half2float(h11))};
                    // q_lo batch layout shares cb scaling of sC? lo arrays are contiguous per-row ldclo
                    *reinterpret_cast<__half2*>(Clo + (size_t)m * ldclo + n) = pl0;
                    *reinterpret_cast<__half2*>(Clo + (size_t)(m + 8) * ldclo + n) = pl1;
                }
            }
        }
    }
}

// ---------------- aux kernels ----------------
__global__ __launch_bounds__(256) void split_f16(const float* __restrict__ in,
                                                 fp16* __restrict__ hi, fp16* __restrict__ lo, int n4)
{
    int i = blockIdx.x * 256 + threadIdx.x;
    if (i >= n4) return;
    float4 v = reinterpret_cast<const float4*>(in)[i];
    __align__(8) fp16 h[4];
    __align__(8) fp16 l[4];
    float f[4] = {v.x, v.y, v.z, v.w};
    #pragma unroll
    for (int j = 0; j < 4; j++) {
        h[j] = __float2half(f[j]);
        l[j] = __float2half(f[j] - __half2float(h[j]));
    }
    reinterpret_cast<uint2*>(hi)[i] = *reinterpret_cast<uint2*>(h);
    reinterpret_cast<uint2*>(lo)[i] = *reinterpret_cast<uint2*>(l);
}

__global__ void concat_bias(const float* a, const float* b, const float* c, float* o)
{
    int i = blockIdx.x * 256 + threadIdx.x;
    if (i < DM)            o[i] = a[i];
    else if (i < 2 * DM)   o[i] = b[i - DM];
    else if (i < 3 * DM)   o[i] = c[i - 2 * DM];
}

// W [K=DM, N=DM] fp32 -> wt fp16 [N, K] (transposed, single-rounded), z selects Wq/Wk/Wv
__global__ void transpose_w_f16(const float* __restrict__ Wq, const float* __restrict__ Wk,
                                const float* __restrict__ Wv, fp16* __restrict__ wt)
{
    __shared__ float t[32][33];
    const float* W = blockIdx.z == 0 ? Wq : blockIdx.z == 1 ? Wk : Wv;
    fp16* o = wt + (size_t)blockIdx.z * DM * DM;
    const int n0 = blockIdx.x * 32, k0 = blockIdx.y * 32;
    const int tx = threadIdx.x, ty = threadIdx.y;
    #pragma unroll
    for (int r = 0; r < 4; r++)
        t[ty + 8 * r][tx] = W[(size_t)(k0 + ty + 8 * r) * DM + n0 + tx];
    __syncthreads();
    #pragma unroll
    for (int r = 0; r < 4; r++)
        o[(size_t)(n0 + ty + 8 * r) * DM + k0 + tx] = __float2half(t[tx][ty + 8 * r]);
}

// V slice of [B][SEQ][3*DM] (fp16, stride ldin) -> [B][DM][SEQ] fp16 transpose
__global__ void transpose_f16(const fp16* __restrict__ in, fp16* __restrict__ out, int ldin)
{
    __shared__ fp16 t[32][33];
    const size_t ib = (size_t)blockIdx.z * SEQ * ldin;
    const size_t ob = (size_t)blockIdx.z * DM * SEQ;
    const int s0 = blockIdx.y * 32, d0 = blockIdx.x * 32;
    const int tx = threadIdx.x, ty = threadIdx.y;
    #pragma unroll
    for (int r = 0; r < 4; r++)
        t[ty + 8 * r][tx] = in[ib + (size_t)(s0 + ty + 8 * r) * ldin + d0 + tx];
    __syncthreads();
    #pragma unroll
    for (int r = 0; r < 4; r++)
        out[ob + (size_t)(d0 + ty + 8 * r) * SEQ + s0 + tx] = t[tx][ty + 8 * r];
}

// row softmax of fp32 scores -> fp16 hi/lo probabilities
__global__ __launch_bounds__(256) void softmax_split(const float* __restrict__ S,
                                                     fp16* __restrict__ Ph, fp16* __restrict__ Pl)
{
    const float* row = S + (size_t)blockIdx.x * SEQ;
    const int tid = threadIdx.x;
    __shared__ float red[8];

    float v[8];
    #pragma unroll
    for (int i = 0; i < 8; i++) v[i] = row[tid + i * 256];

    float m = v[0];
    #pragma unroll
    for (int i = 1; i < 8; i++) m = fmaxf(m, v[i]);
    #pragma unroll
    for (int o = 16; o; o >>= 1) m = fmaxf(m, __shfl_xor_sync(0xffffffffu, m, o));
    if ((tid & 31) == 0) red[tid >> 5] = m;
    __syncthreads();
    float mx = red[0];
    #pragma unroll
    for (int w = 1; w < 8; w++) mx = fmaxf(mx, red[w]);
    __syncthreads();

    float s = 0.f;
    #pragma unroll
    for (int i = 0; i < 8; i++) { v[i] = __expf(v[i] - mx); s += v[i]; }
    #pragma unroll
    for (int o = 16; o; o >>= 1) s += __shfl_xor_sync(0xffffffffu, s, o);
    if ((tid & 31) == 0) red[tid >> 5] = s;
    __syncthreads();
    float tot = red[0];
    #pragma unroll
    for (int w = 1; w < 8; w++) tot += red[w];
    const float inv = 1.0f / tot;

    const size_t ro = (size_t)blockIdx.x * SEQ;
    #pragma unroll
    for (int i = 0; i < 8; i++) {
        float p = v[i] * inv;
        fp16 h = __float2half(p);
        Ph[ro + tid + i * 256] = h;
        Pl[ro + tid + i * 256] = __float2half(p - __half2float(h));
    }
}

// ---------------- launcher ----------------
extern "C" void kernel_launch(void* const* d_in, const int* in_sizes, int n_in,
                              void* d_out, int out_size)
{
    const float* x  = (const float*)d_in[0];
    const float* Wq = (const float*)d_in[1];
    const float* bq = (const float*)d_in[2];
    const float* Wk = (const float*)d_in[3];
    const float* bk = (const float*)d_in[4];
    const float* Wv = (const float*)d_in[5];
    const float* bv = (const float*)d_in[6];
    float* out = (float*)d_out;

    fp16 *xhi, *xlo, *wt, *qkvhi, *qlo, *vt, *phi, *plo;
    float *s, *bias;
    cudaGetSymbolAddress((void**)&xhi, g_xhi);     cudaGetSymbolAddress((void**)&xlo, g_xlo);
    cudaGetSymbolAddress((void**)&wt, g_wt);
    cudaGetSymbolAddress((void**)&qkvhi, g_qkvhi); cudaGetSymbolAddress((void**)&qlo, g_qlo);
    cudaGetSymbolAddress((void**)&vt, g_vt);
    cudaGetSymbolAddress((void**)&phi, g_phi);     cudaGetSymbolAddress((void**)&plo, g_plo);
    cudaGetSymbolAddress((void**)&s, g_s);         cudaGetSymbolAddress((void**)&bias, g_bias);

    cudaFuncSetAttribute(gemm2p, cudaFuncAttributeMaxDynamicSharedMemorySize, GEMM_SMEM);

    const int M = BATCH * SEQ;

    // 1. split x; transpose W (single fp16); concat bias
    split_f16<<<(M * DM / 4 + 255) / 256, 256>>>(x, xhi, xlo, M * DM / 4);
    transpose_w_f16<<<dim3(DM / 32, DM / 32, 3), dim3(32, 8)>>>(Wq, Wk, Wv, wt);
    concat_bias<<<(3 * DM + 255) / 256, 256>>>(bq, bk, bv, bias);

    // 2. fused QKV projection: q -> split hi/lo, k|v -> single fp16
    gemm2p<<<dim3(3 * DM / 128, M / 128, 1), 512, GEMM_SMEM>>>(
        xhi, xlo, wt, bias, 1.f,
        nullptr, qkvhi, qlo,
        DM, DM, DM, DM, 3 * DM, DM, DM, 0, 0, 0, 0);

    // 3. V^T (single fp16)
    transpose_f16<<<dim3(DM / 32, SEQ / 32, BATCH), dim3(32, 8)>>>(qkvhi + 2 * DM, vt, 3 * DM);

    // 4. scores = scale * Q @ K^T (fp32 out); A = q hi/lo, B = k single
    gemm2p<<<dim3(SEQ / 128, SEQ / 128, BATCH), 512, GEMM_SMEM>>>(
        qkvhi, qlo, qkvhi + DM, nullptr, 0.03125f,
        s, nullptr, nullptr,
        DM, 3 * DM, DM, 3 * DM, SEQ, 0, 0,
        (size_t)SEQ * 3 * DM, (size_t)SEQ * DM, (size_t)SEQ * 3 * DM, (size_t)SEQ * SEQ);

    // 5. softmax -> fp16 hi/lo probs
    softmax_split<<<BATCH * SEQ, 256>>>(s, phi, plo);

    // 6. out = attn @ V (fp32 out); A = p hi/lo, B = v^t single
    gemm2p<<<dim3(DM / 128, SEQ / 128, BATCH), 512, GEMM_SMEM>>>(
        phi, plo, vt, nullptr, 1.f,
        out, nullptr, nullptr,
        SEQ, SEQ, SEQ, SEQ, DM, 0, 0,
        (size_t)SEQ * SEQ, (size_t)SEQ * SEQ, (size_t)DM * SEQ, (size_t)SEQ * DM);
}

// round 6
// speedup vs baseline: 4.2994x; 1.1706x over previous
#include <cuda_runtime.h>
#include <cuda_fp16.h>
#include <stdint.h>

#define BATCH 4
#define SEQ   2048
#define DM    1024
typedef __half fp16;

// ---------------- scratch (__device__ globals; no allocation) ----------------
__device__ fp16 g_xhi[(size_t)BATCH*SEQ*DM];
__device__ fp16 g_xlo[(size_t)BATCH*SEQ*DM];
__device__ fp16 g_wt[(size_t)3*DM*DM];            // W^T single fp16: [3*DM][DM]
__device__ float g_bias[3*DM];
__device__ fp16 g_qkvhi[(size_t)BATCH*SEQ*3*DM];  // [B*S][3DM]: q_hi | k | v
__device__ fp16 g_qlo[(size_t)BATCH*SEQ*DM];      // q_lo only
__device__ fp16 g_vt[(size_t)BATCH*DM*SEQ];       // V^T single
__device__ float g_s[(size_t)BATCH*SEQ*SEQ];      // scores fp32
__device__ fp16 g_phi[(size_t)BATCH*SEQ*SEQ];     // attn probs (single fp16)

// ---------------- helpers ----------------
__device__ __forceinline__ uint32_t s2u(const void* p) {
    uint32_t a;
    asm("{ .reg .u64 t; cvta.to.shared.u64 t, %1; cvt.u32.u64 %0, t; }" : "=r"(a) : "l"(p));
    return a;
}
__device__ __forceinline__ void ldsm4(uint32_t* r, uint32_t addr) {
    asm volatile("ldmatrix.sync.aligned.m8n8.x4.shared.b16 {%0,%1,%2,%3}, [%4];"
                 : "=r"(r[0]), "=r"(r[1]), "=r"(r[2]), "=r"(r[3]) : "r"(addr));
}
__device__ __forceinline__ void mma16816(float* d, const uint32_t* a, uint32_t b0, uint32_t b1) {
    asm volatile(
        "mma.sync.aligned.m16n8k16.row.col.f32.f16.f16.f32 "
        "{%0,%1,%2,%3}, {%4,%5,%6,%7}, {%8,%9}, {%0,%1,%2,%3};"
        : "+f"(d[0]), "+f"(d[1]), "+f"(d[2]), "+f"(d[3])
        : "r"(a[0]), "r"(a[1]), "r"(a[2]), "r"(a[3]), "r"(b0), "r"(b1));
}

// ---------------- HMMA GEMM: C = scale*(A@B^T) [+bias] ----------------
// NPROD=2: A split hi/lo (Ozaki 2-product). NPROD=1: A single fp16.
// B single fp16 [N,K]. Out fp32 Cf OR fp16 Chi (+Clo when n0<splitn).
// CTA 128x128, BK=64, 3 stages, 512 threads, warp tile 32x32,
// register double-buffered fragments.
#define BK      64
#define TILE_B  16384                    // 128 rows * 128B

template<int NPROD>
__global__ __launch_bounds__(512, 1) void gemm2p(
    const fp16* __restrict__ Ahi, const fp16* __restrict__ Alo,
    const fp16* __restrict__ B,
    const float* __restrict__ bias, float scale,
    float* __restrict__ Cf, fp16* __restrict__ Chi, fp16* __restrict__ Clo,
    int K, int lda, int ldalo, int ldb, int ldc, int ldclo, int splitn,
    size_t sA, size_t sAlo, size_t sB, size_t sC)
{
    constexpr int NT = NPROD + 1;            // tiles per stage
    constexpr uint32_t STAGE_B = NT * TILE_B;
    extern __shared__ char smem[];
    const uint32_t sb = s2u(smem);
    const int tid = threadIdx.x;
    const int wid = tid >> 5, lane = tid & 31;
    const int wm = wid & 3, wn = wid >> 2;           // warp grid 4 (m) x 4 (n)
    const int m0 = blockIdx.y * 128, n0 = blockIdx.x * 128;
    const int NC = K / BK;

    const fp16* bAhi = Ahi + (size_t)blockIdx.z * sA   + (size_t)m0 * lda;
    const fp16* bAlo = (NPROD == 2) ? Alo + (size_t)blockIdx.z * sAlo + (size_t)m0 * ldalo : nullptr;
    const fp16* bB   = B   + (size_t)blockIdx.z * sB   + (size_t)n0 * ldb;

    auto load_chunk = [&](int c) {
        const uint32_t stg = sb + (uint32_t)(c % 3) * STAGE_B;
        const int k0 = c * BK;
        #pragma unroll
        for (int i = 0; i < 2 * NT; i++) {
            const int t = i >> 1;                       // 0: Ahi, [1: Alo,] last: B
            const int sub = tid + (i & 1) * 512;        // 0..1023
            const int row = sub >> 3, col = sub & 7;    // 128 rows x 8 16B-cols
            const int ld = (t == 0) ? lda : (t == NT - 1) ? ldb : ldalo;
            const fp16* src = (t == 0 ? bAhi : t == NT - 1 ? bB : bAlo)
                              + (size_t)row * ld + k0 + col * 8;
            uint32_t off = (uint32_t)(row * 128 + col * 16);
            uint32_t dst = stg + (uint32_t)t * TILE_B + (off ^ ((off >> 3) & 0x70));
            asm volatile("cp.async.cg.shared.global [%0], [%1], 16;" :: "r"(dst), "l"(src) : "memory");
        }
        asm volatile("cp.async.commit_group;" ::: "memory");
    };

    // per-lane ldmatrix addressing (SW128 rows of 128B)
    const int rlane = (lane & 7) + ((lane >> 3) & 1) * 8;
    const uint32_t xlane = (uint32_t)((rlane & 7) * 16);
    const uint32_t kbl = (uint32_t)((lane >> 4) * 16);
    uint32_t aoff[2], boff[2], kx[4];
    #pragma unroll
    for (int mf = 0; mf < 2; mf++) aoff[mf] = (uint32_t)((wm * 32 + mf * 16 + rlane) << 7);
    #pragma unroll
    for (int ng = 0; ng < 2; ng++) boff[ng] = (uint32_t)((wn * 32 + ng * 16 + rlane) << 7);
    #pragma unroll
    for (int ks = 0; ks < 4; ks++) kx[ks] = ((uint32_t)(ks * 32) + kbl) ^ xlane;

    float acc[2][4][4] = {};
    uint32_t ah[2][2][4], bt[2][2][4], al[2][4];

    load_chunk(0);
    if (NC > 1) load_chunk(1);

    for (int c = 0; c < NC; ++c) {
        if (c + 1 < NC) asm volatile("cp.async.wait_group 1;" ::: "memory");
        else            asm volatile("cp.async.wait_group 0;" ::: "memory");
        __syncthreads();                       // chunk c visible; stage (c+2)%3 free
        if (c + 2 < NC) load_chunk(c + 2);

        const uint32_t stg = sb + (uint32_t)(c % 3) * STAGE_B;
        const uint32_t sAh = stg;
        const uint32_t sAl = stg + TILE_B;                    // valid when NPROD==2
        const uint32_t sB_ = stg + (uint32_t)(NT - 1) * TILE_B;

        // prime fragments for ks=0
        ldsm4(ah[0][0], sAh + aoff[0] + kx[0]);
        ldsm4(ah[0][1], sAh + aoff[1] + kx[0]);
        ldsm4(bt[0][0], sB_ + boff[0] + kx[0]);
        ldsm4(bt[0][1], sB_ + boff[1] + kx[0]);

        #pragma unroll
        for (int ks = 0; ks < 4; ks++) {
            const int b = ks & 1;
            // A-lo for this step (consumed after the 8 hi-MMAs below)
            if (NPROD == 2) {
                ldsm4(al[0], sAl + aoff[0] + kx[ks]);
                ldsm4(al[1], sAl + aoff[1] + kx[ks]);
            }
            // prefetch next step's hi/B fragments
            if (ks < 3) {
                ldsm4(ah[b ^ 1][0], sAh + aoff[0] + kx[ks + 1]);
                ldsm4(ah[b ^ 1][1], sAh + aoff[1] + kx[ks + 1]);
                ldsm4(bt[b ^ 1][0], sB_ + boff[0] + kx[ks + 1]);
                ldsm4(bt[b ^ 1][1], sB_ + boff[1] + kx[ks + 1]);
            }
            #pragma unroll
            for (int mf = 0; mf < 2; mf++)
                #pragma unroll
                for (int nf = 0; nf < 4; nf++)
                    mma16816(acc[mf][nf], ah[b][mf],
                             bt[b][nf >> 1][nf & 1], bt[b][nf >> 1][(nf & 1) + 2]);
            if (NPROD == 2) {
                #pragma unroll
                for (int mf = 0; mf < 2; mf++)
                    #pragma unroll
                    for (int nf = 0; nf < 4; nf++)
                        mma16816(acc[mf][nf], al[mf],
                                 bt[b][nf >> 1][nf & 1], bt[b][nf >> 1][(nf & 1) + 2]);
            }
        }
    }

    // ---------------- epilogue ----------------
    const bool do_split = Clo && (n0 < splitn);
    const size_t cb = (size_t)blockIdx.z * sC;
    #pragma unroll
    for (int mf = 0; mf < 2; mf++) {
        #pragma unroll
        for (int nf = 0; nf < 4; nf++) {
            const int m = m0 + wm * 32 + mf * 16 + (lane >> 2);
            const int n = n0 + wn * 32 + nf * 8 + 2 * (lane & 3);
            const float b0 = bias ? bias[n] : 0.f;
            const float b1 = bias ? bias[n + 1] : 0.f;
            float v00 = acc[mf][nf][0] * scale + b0;
            float v01 = acc[mf][nf][1] * scale + b1;
            float v10 = acc[mf][nf][2] * scale + b0;
            float v11 = acc[mf][nf][3] * scale + b1;
            if (Cf) {
                float2 o0 = {v00, v01}, o1 = {v10, v11};
                *reinterpret_cast<float2*>(Cf + cb + (size_t)m * ldc + n)       = o0;
                *reinterpret_cast<float2*>(Cf + cb + (size_t)(m + 8) * ldc + n) = o1;
            } else {
                fp16 h00 = __float2half(v00), h01 = __float2half(v01);
                fp16 h10 = __float2half(v10), h11 = __float2half(v11);
                __half2 ph0 = {h00, h01}, ph1 = {h10, h11};
                *reinterpret_cast<__half2*>(Chi + cb + (size_t)m * ldc + n)       = ph0;
                *reinterpret_cast<__half2*>(Chi + cb + (size_t)(m + 8) * ldc + n) = ph1;
                if (do_split) {
                    __half2 pl0 = {__float2half(v00 - __half2float(h00)),
                                   __float2half(v01 - __half2float(h01))};
                    __half2 pl1 = {__float2half(v10 - __half2float(h10)),
                                   __float2half(v11 - __half2float(h11))};
                    *reinterpret_cast<__half2*>(Clo + (size_t)m * ldclo + n)       = pl0;
                    *reinterpret_cast<__half2*>(Clo + (size_t)(m + 8) * ldclo + n) = pl1;
                }
            }
        }
    }
}

// ---------------- aux kernels ----------------
__global__ __launch_bounds__(256) void split_f16(const float* __restrict__ in,
                                                 fp16* __restrict__ hi, fp16* __restrict__ lo, int n4)
{
    int i = blockIdx.x * 256 + threadIdx.x;
    if (i >= n4) return;
    float4 v = reinterpret_cast<const float4*>(in)[i];
    __align__(8) fp16 h[4];
    __align__(8) fp16 l[4];
    float f[4] = {v.x, v.y, v.z, v.w};
    #pragma unroll
    for (int j = 0; j < 4; j++) {
        h[j] = __float2half(f[j]);
        l[j] = __float2half(f[j] - __half2float(h[j]));
    }
    reinterpret_cast<uint2*>(hi)[i] = *reinterpret_cast<uint2*>(h);
    reinterpret_cast<uint2*>(lo)[i] = *reinterpret_cast<uint2*>(l);
}

__global__ void concat_bias(const float* a, const float* b, const float* c, float* o)
{
    int i = blockIdx.x * 256 + threadIdx.x;
    if (i < DM)            o[i] = a[i];
    else if (i < 2 * DM)   o[i] = b[i - DM];
    else if (i < 3 * DM)   o[i] = c[i - 2 * DM];
}

// W [K=DM, N=DM] fp32 -> wt fp16 [N, K] (transposed, single-rounded), z selects Wq/Wk/Wv
__global__ void transpose_w_f16(const float* __restrict__ Wq, const float* __restrict__ Wk,
                                const float* __restrict__ Wv, fp16* __restrict__ wt)
{
    __shared__ float t[32][33];
    const float* W = blockIdx.z == 0 ? Wq : blockIdx.z == 1 ? Wk : Wv;
    fp16* o = wt + (size_t)blockIdx.z * DM * DM;
    const int n0 = blockIdx.x * 32, k0 = blockIdx.y * 32;
    const int tx = threadIdx.x, ty = threadIdx.y;
    #pragma unroll
    for (int r = 0; r < 4; r++)
        t[ty + 8 * r][tx] = W[(size_t)(k0 + ty + 8 * r) * DM + n0 + tx];
    __syncthreads();
    #pragma unroll
    for (int r = 0; r < 4; r++)
        o[(size_t)(n0 + ty + 8 * r) * DM + k0 + tx] = __float2half(t[tx][ty + 8 * r]);
}

// V slice of [B][SEQ][3*DM] (fp16, stride ldin) -> [B][DM][SEQ] fp16 transpose
__global__ void transpose_f16(const fp16* __restrict__ in, fp16* __restrict__ out, int ldin)
{
    __shared__ fp16 t[32][33];
    const size_t ib = (size_t)blockIdx.z * SEQ * ldin;
    const size_t ob = (size_t)blockIdx.z * DM * SEQ;
    const int s0 = blockIdx.y * 32, d0 = blockIdx.x * 32;
    const int tx = threadIdx.x, ty = threadIdx.y;
    #pragma unroll
    for (int r = 0; r < 4; r++)
        t[ty + 8 * r][tx] = in[ib + (size_t)(s0 + ty + 8 * r) * ldin + d0 + tx];
    __syncthreads();
    #pragma unroll
    for (int r = 0; r < 4; r++)
        out[ob + (size_t)(d0 + ty + 8 * r) * SEQ + s0 + tx] = t[tx][ty + 8 * r];
}

// row softmax of fp32 scores -> single fp16 probabilities
__global__ __launch_bounds__(256) void softmax_f16(const float* __restrict__ S,
                                                   fp16* __restrict__ Ph)
{
    const float* row = S + (size_t)blockIdx.x * SEQ;
    const int tid = threadIdx.x;
    __shared__ float red[8];

    float v[8];
    #pragma unroll
    for (int i = 0; i < 8; i++) v[i] = row[tid + i * 256];

    float m = v[0];
    #pragma unroll
    for (int i = 1; i < 8; i++) m = fmaxf(m, v[i]);
    #pragma unroll
    for (int o = 16; o; o >>= 1) m = fmaxf(m, __shfl_xor_sync(0xffffffffu, m, o));
    if ((tid & 31) == 0) red[tid >> 5] = m;
    __syncthreads();
    float mx = red[0];
    #pragma unroll
    for (int w = 1; w < 8; w++) mx = fmaxf(mx, red[w]);
    __syncthreads();

    float s = 0.f;
    #pragma unroll
    for (int i = 0; i < 8; i++) { v[i] = __expf(v[i] - mx); s += v[i]; }
    #pragma unroll
    for (int o = 16; o; o >>= 1) s += __shfl_xor_sync(0xffffffffu, s, o);
    if ((tid & 31) == 0) red[tid >> 5] = s;
    __syncthreads();
    float tot = red[0];
    #pragma unroll
    for (int w = 1; w < 8; w++) tot += red[w];
    const float inv = 1.0f / tot;

    const size_t ro = (size_t)blockIdx.x * SEQ;
    #pragma unroll
    for (int i = 0; i < 8; i++)
        Ph[ro + tid + i * 256] = __float2half(v[i] * inv);
}

// ---------------- launcher ----------------
extern "C" void kernel_launch(void* const* d_in, const int* in_sizes, int n_in,
                              void* d_out, int out_size)
{
    const float* x  = (const float*)d_in[0];
    const float* Wq = (const float*)d_in[1];
    const float* bq = (const float*)d_in[2];
    const float* Wk = (const float*)d_in[3];
    const float* bk = (const float*)d_in[4];
    const float* Wv = (const float*)d_in[5];
    const float* bv = (const float*)d_in[6];
    float* out = (float*)d_out;

    fp16 *xhi, *xlo, *wt, *qkvhi, *qlo, *vt, *phi;
    float *s, *bias;
    cudaGetSymbolAddress((void**)&xhi, g_xhi);     cudaGetSymbolAddress((void**)&xlo, g_xlo);
    cudaGetSymbolAddress((void**)&wt, g_wt);
    cudaGetSymbolAddress((void**)&qkvhi, g_qkvhi); cudaGetSymbolAddress((void**)&qlo, g_qlo);
    cudaGetSymbolAddress((void**)&vt, g_vt);
    cudaGetSymbolAddress((void**)&phi, g_phi);
    cudaGetSymbolAddress((void**)&s, g_s);         cudaGetSymbolAddress((void**)&bias, g_bias);

    const int SMEM2 = 3 * 3 * TILE_B;   // 144 KB
    const int SMEM1 = 3 * 2 * TILE_B;   //  96 KB
    cudaFuncSetAttribute(gemm2p<2>, cudaFuncAttributeMaxDynamicSharedMemorySize, SMEM2);
    cudaFuncSetAttribute(gemm2p<1>, cudaFuncAttributeMaxDynamicSharedMemorySize, SMEM1);

    const int M = BATCH * SEQ;

    // 1. split x; transpose W (single fp16); concat bias
    split_f16<<<(M * DM / 4 + 255) / 256, 256>>>(x, xhi, xlo, M * DM / 4);
    transpose_w_f16<<<dim3(DM / 32, DM / 32, 3), dim3(32, 8)>>>(Wq, Wk, Wv, wt);
    concat_bias<<<(3 * DM + 255) / 256, 256>>>(bq, bk, bv, bias);

    // 2. fused QKV projection: q -> split hi/lo, k|v -> single fp16
    gemm2p<2><<<dim3(3 * DM / 128, M / 128, 1), 512, SMEM2>>>(
        xhi, xlo, wt, bias, 1.f,
        nullptr, qkvhi, qlo,
        DM, DM, DM, DM, 3 * DM, DM, DM, 0, 0, 0, 0);

    // 3. V^T (single fp16)
    transpose_f16<<<dim3(DM / 32, SEQ / 32, BATCH), dim3(32, 8)>>>(qkvhi + 2 * DM, vt, 3 * DM);

    // 4. scores = scale * Q @ K^T (fp32 out); A = q hi/lo, B = k single
    gemm2p<2><<<dim3(SEQ / 128, SEQ / 128, BATCH), 512, SMEM2>>>(
        qkvhi, qlo, qkvhi + DM, nullptr, 0.03125f,
        s, nullptr, nullptr,
        DM, 3 * DM, DM, 3 * DM, SEQ, 0, 0,
        (size_t)SEQ * 3 * DM, (size_t)SEQ * DM, (size_t)SEQ * 3 * DM, (size_t)SEQ * SEQ);

    // 5. softmax -> single fp16 probs
    softmax_f16<<<BATCH * SEQ, 256>>>(s, phi);

    // 6. out = attn @ V (fp32 out); A = p single, B = v^t single
    gemm2p<1><<<dim3(DM / 128, SEQ / 128, BATCH), 512, SMEM1>>>(
        phi, nullptr, vt, nullptr, 1.f,
        out, nullptr, nullptr,
        SEQ, SEQ, 0, SEQ, DM, 0, 0,
        (size_t)SEQ * SEQ, 0, (size_t)DM * SEQ, (size_t)SEQ * DM);
}

// round 7
// speedup vs baseline: 4.7984x; 1.1161x over previous
#include <cuda_runtime.h>
#include <cuda_fp16.h>
#include <stdint.h>

#define BATCH 4
#define SEQ   2048
#define DM    1024
typedef __half fp16;

// ---------------- scratch (__device__ globals; no allocation) ----------------
__device__ fp16 g_xhi[(size_t)BATCH*SEQ*DM];
__device__ fp16 g_xlo[(size_t)BATCH*SEQ*DM];
__device__ fp16 g_wt[(size_t)3*DM*DM];            // W^T single fp16: [3*DM][DM]
__device__ float g_bias[3*DM];
__device__ fp16 g_qkvhi[(size_t)BATCH*SEQ*3*DM];  // [B*S][3DM]: q_hi | k | v
__device__ fp16 g_qlo[(size_t)BATCH*SEQ*DM];      // q_lo only
__device__ fp16 g_vt[(size_t)BATCH*DM*SEQ];       // V^T single
__device__ float g_s[(size_t)BATCH*SEQ*SEQ];      // scores fp32
__device__ fp16 g_phi[(size_t)BATCH*SEQ*SEQ];     // attn probs (single fp16)

// ---------------- helpers ----------------
__device__ __forceinline__ uint32_t s2u(const void* p) {
    uint32_t a;
    asm("{ .reg .u64 t; cvta.to.shared.u64 t, %1; cvt.u32.u64 %0, t; }" : "=r"(a) : "l"(p));
    return a;
}
__device__ __forceinline__ void ldsm4(uint32_t* r, uint32_t addr) {
    asm volatile("ldmatrix.sync.aligned.m8n8.x4.shared.b16 {%0,%1,%2,%3}, [%4];"
                 : "=r"(r[0]), "=r"(r[1]), "=r"(r[2]), "=r"(r[3]) : "r"(addr));
}
__device__ __forceinline__ void mma16816(float* d, const uint32_t* a, uint32_t b0, uint32_t b1) {
    asm volatile(
        "mma.sync.aligned.m16n8k16.row.col.f32.f16.f16.f32 "
        "{%0,%1,%2,%3}, {%4,%5,%6,%7}, {%8,%9}, {%0,%1,%2,%3};"
        : "+f"(d[0]), "+f"(d[1]), "+f"(d[2]), "+f"(d[3])
        : "r"(a[0]), "r"(a[1]), "r"(a[2]), "r"(a[3]), "r"(b0), "r"(b1));
}

// ---------------- HMMA GEMM: C = scale*(A@B^T) [+bias] ----------------
// NPROD=2: A split hi/lo (2-product). NPROD=1: A single fp16.
// B single fp16 [N,K]. Out fp32 Cf OR fp16 Chi (+Clo when n0<splitn).
// CTA 128x128, BK=64, 256 threads (8 warps, warp tile 32x64), 2 CTAs/SM.
// Stages: NPROD==2 -> 2 (96 KB), NPROD==1 -> 3 (96 KB).
#define BK      64
#define TILE_B  16384                    // 128 rows * 128B

template<int NPROD>
__global__ __launch_bounds__(256, 2) void gemmw(
    const fp16* __restrict__ Ahi, const fp16* __restrict__ Alo,
    const fp16* __restrict__ B,
    const float* __restrict__ bias, float scale,
    float* __restrict__ Cf, fp16* __restrict__ Chi, fp16* __restrict__ Clo,
    int K, int lda, int ldalo, int ldb, int ldc, int ldclo, int splitn,
    size_t sA, size_t sAlo, size_t sB, size_t sC)
{
    constexpr int NT = NPROD + 1;            // tiles per stage
    constexpr int NSTG = (NPROD == 2) ? 2 : 3;
    constexpr uint32_t STAGE_B = NT * TILE_B;
    extern __shared__ char smem[];
    const uint32_t sb = s2u(smem);
    const int tid = threadIdx.x;
    const int wid = tid >> 5, lane = tid & 31;
    const int wm = wid & 3, wn = wid >> 2;           // warp grid 4 (m) x 2 (n)
    const int m0 = blockIdx.y * 128, n0 = blockIdx.x * 128;
    const int NC = K / BK;

    const fp16* bAhi = Ahi + (size_t)blockIdx.z * sA   + (size_t)m0 * lda;
    const fp16* bAlo = (NPROD == 2) ? Alo + (size_t)blockIdx.z * sAlo + (size_t)m0 * ldalo : nullptr;
    const fp16* bB   = B   + (size_t)blockIdx.z * sB   + (size_t)n0 * ldb;

    auto load_chunk = [&](int c) {
        const uint32_t stg = sb + (uint32_t)(c % NSTG) * STAGE_B;
        const int k0 = c * BK;
        #pragma unroll
        for (int i = 0; i < 4 * NT; i++) {
            const int t = i >> 2;                       // 0: Ahi, [1: Alo,] last: B
            const int sub = tid + (i & 3) * 256;        // 0..1023
            const int row = sub >> 3, col = sub & 7;    // 128 rows x 8 16B-cols
            const int ld = (t == 0) ? lda : (t == NT - 1) ? ldb : ldalo;
            const fp16* src = (t == 0 ? bAhi : t == NT - 1 ? bB : bAlo)
                              + (size_t)row * ld + k0 + col * 8;
            uint32_t off = (uint32_t)(row * 128 + col * 16);
            uint32_t dst = stg + (uint32_t)t * TILE_B + (off ^ ((off >> 3) & 0x70));
            asm volatile("cp.async.cg.shared.global [%0], [%1], 16;" :: "r"(dst), "l"(src) : "memory");
        }
        asm volatile("cp.async.commit_group;" ::: "memory");
    };

    // per-lane ldmatrix addressing (SW128 rows of 128B)
    const int rlane = (lane & 7) + ((lane >> 3) & 1) * 8;
    const uint32_t xlane = (uint32_t)((rlane & 7) * 16);
    const uint32_t kbl = (uint32_t)((lane >> 4) * 16);
    uint32_t aoff[2], boff[4], kx[4];
    #pragma unroll
    for (int mf = 0; mf < 2; mf++) aoff[mf] = (uint32_t)((wm * 32 + mf * 16 + rlane) << 7);
    #pragma unroll
    for (int g = 0; g < 4; g++) boff[g] = (uint32_t)((wn * 64 + g * 16 + rlane) << 7);
    #pragma unroll
    for (int ks = 0; ks < 4; ks++) kx[ks] = ((uint32_t)(ks * 32) + kbl) ^ xlane;

    float acc[2][8][4] = {};

    #pragma unroll
    for (int p = 0; p < NSTG - 1; p++)
        if (p < NC) load_chunk(p);

    for (int c = 0; c < NC; ++c) {
        if (c + NSTG - 1 < NC) {
            if (NSTG == 3) asm volatile("cp.async.wait_group 1;" ::: "memory");
            else           asm volatile("cp.async.wait_group 0;" ::: "memory");
        } else {
            asm volatile("cp.async.wait_group 0;" ::: "memory");
        }
        __syncthreads();                       // chunk c visible; oldest stage free
        if (c + NSTG - 1 < NC) load_chunk(c + NSTG - 1);

        const uint32_t stg = sb + (uint32_t)(c % NSTG) * STAGE_B;
        const uint32_t sAh = stg;
        const uint32_t sAl = stg + TILE_B;                    // valid when NPROD==2
        const uint32_t sB_ = stg + (uint32_t)(NT - 1) * TILE_B;

        #pragma unroll
        for (int ks = 0; ks < 4; ks++) {
            uint32_t ah[2][4], al[2][4], bf[8][2];
            ldsm4(ah[0], sAh + aoff[0] + kx[ks]);
            ldsm4(ah[1], sAh + aoff[1] + kx[ks]);
            #pragma unroll
            for (int g = 0; g < 4; g++) {
                uint32_t t[4];
                ldsm4(t, sB_ + boff[g] + kx[ks]);
                bf[2*g][0] = t[0]; bf[2*g+1][0] = t[1];
                bf[2*g][1] = t[2]; bf[2*g+1][1] = t[3];
            }
            if (NPROD == 2) {                   // issued early; hidden by hi-MMAs
                ldsm4(al[0], sAl + aoff[0] + kx[ks]);
                ldsm4(al[1], sAl + aoff[1] + kx[ks]);
            }
            #pragma unroll
            for (int mf = 0; mf < 2; mf++)
                #pragma unroll
                for (int nf = 0; nf < 8; nf++)
                    mma16816(acc[mf][nf], ah[mf], bf[nf][0], bf[nf][1]);
            if (NPROD == 2) {
                #pragma unroll
                for (int mf = 0; mf < 2; mf++)
                    #pragma unroll
                    for (int nf = 0; nf < 8; nf++)
                        mma16816(acc[mf][nf], al[mf], bf[nf][0], bf[nf][1]);
            }
        }
    }

    // ---------------- epilogue ----------------
    const bool do_split = Clo && (n0 < splitn);
    const size_t cb = (size_t)blockIdx.z * sC;
    #pragma unroll
    for (int mf = 0; mf < 2; mf++) {
        #pragma unroll
        for (int nf = 0; nf < 8; nf++) {
            const int m = m0 + wm * 32 + mf * 16 + (lane >> 2);
            const int n = n0 + wn * 64 + nf * 8 + 2 * (lane & 3);
            const float b0 = bias ? bias[n] : 0.f;
            const float b1 = bias ? bias[n + 1] : 0.f;
            float v00 = acc[mf][nf][0] * scale + b0;
            float v01 = acc[mf][nf][1] * scale + b1;
            float v10 = acc[mf][nf][2] * scale + b0;
            float v11 = acc[mf][nf][3] * scale + b1;
            if (Cf) {
                float2 o0 = {v00, v01}, o1 = {v10, v11};
                *reinterpret_cast<float2*>(Cf + cb + (size_t)m * ldc + n)       = o0;
                *reinterpret_cast<float2*>(Cf + cb + (size_t)(m + 8) * ldc + n) = o1;
            } else {
                fp16 h00 = __float2half(v00), h01 = __float2half(v01);
                fp16 h10 = __float2half(v10), h11 = __float2half(v11);
                __half2 ph0 = {h00, h01}, ph1 = {h10, h11};
                *reinterpret_cast<__half2*>(Chi + cb + (size_t)m * ldc + n)       = ph0;
                *reinterpret_cast<__half2*>(Chi + cb + (size_t)(m + 8) * ldc + n) = ph1;
                if (do_split) {
                    __half2 pl0 = {__float2half(v00 - __half2float(h00)),
                                   __float2half(v01 - __half2float(h01))};
                    __half2 pl1 = {__float2half(v10 - __half2float(h10)),
                                   __float2half(v11 - __half2float(h11))};
                    *reinterpret_cast<__half2*>(Clo + (size_t)m * ldclo + n)       = pl0;
                    *reinterpret_cast<__half2*>(Clo + (size_t)(m + 8) * ldclo + n) = pl1;
                }
            }
        }
    }
}

// ---------------- aux kernels ----------------
__global__ __launch_bounds__(256) void split_f16(const float* __restrict__ in,
                                                 fp16* __restrict__ hi, fp16* __restrict__ lo, int n4)
{
    int i = blockIdx.x * 256 + threadIdx.x;
    if (i >= n4) return;
    float4 v = reinterpret_cast<const float4*>(in)[i];
    __align__(8) fp16 h[4];
    __align__(8) fp16 l[4];
    float f[4] = {v.x, v.y, v.z, v.w};
    #pragma unroll
    for (int j = 0; j < 4; j++) {
        h[j] = __float2half(f[j]);
        l[j] = __float2half(f[j] - __half2float(h[j]));
    }
    reinterpret_cast<uint2*>(hi)[i] = *reinterpret_cast<uint2*>(h);
    reinterpret_cast<uint2*>(lo)[i] = *reinterpret_cast<uint2*>(l);
}

__global__ void concat_bias(const float* a, const float* b, const float* c, float* o)
{
    int i = blockIdx.x * 256 + threadIdx.x;
    if (i < DM)            o[i] = a[i];
    else if (i < 2 * DM)   o[i] = b[i - DM];
    else if (i < 3 * DM)   o[i] = c[i - 2 * DM];
}

// W [K=DM, N=DM] fp32 -> wt fp16 [N, K] (transposed, single-rounded), z selects Wq/Wk/Wv
__global__ void transpose_w_f16(const float* __restrict__ Wq, const float* __restrict__ Wk,
                                const float* __restrict__ Wv, fp16* __restrict__ wt)
{
    __shared__ float t[32][33];
    const float* W = blockIdx.z == 0 ? Wq : blockIdx.z == 1 ? Wk : Wv;
    fp16* o = wt + (size_t)blockIdx.z * DM * DM;
    const int n0 = blockIdx.x * 32, k0 = blockIdx.y * 32;
    const int tx = threadIdx.x, ty = threadIdx.y;
    #pragma unroll
    for (int r = 0; r < 4; r++)
        t[ty + 8 * r][tx] = W[(size_t)(k0 + ty + 8 * r) * DM + n0 + tx];
    __syncthreads();
    #pragma unroll
    for (int r = 0; r < 4; r++)
        o[(size_t)(n0 + ty + 8 * r) * DM + k0 + tx] = __float2half(t[tx][ty + 8 * r]);
}

// V slice of [B][SEQ][3*DM] (fp16, stride ldin) -> [B][DM][SEQ] fp16 transpose
__global__ void transpose_f16(const fp16* __restrict__ in, fp16* __restrict__ out, int ldin)
{
    __shared__ fp16 t[32][33];
    const size_t ib = (size_t)blockIdx.z * SEQ * ldin;
    const size_t ob = (size_t)blockIdx.z * DM * SEQ;
    const int s0 = blockIdx.y * 32, d0 = blockIdx.x * 32;
    const int tx = threadIdx.x, ty = threadIdx.y;
    #pragma unroll
    for (int r = 0; r < 4; r++)
        t[ty + 8 * r][tx] = in[ib + (size_t)(s0 + ty + 8 * r) * ldin + d0 + tx];
    __syncthreads();
    #pragma unroll
    for (int r = 0; r < 4; r++)
        out[ob + (size_t)(d0 + ty + 8 * r) * SEQ + s0 + tx] = t[tx][ty + 8 * r];
}

// row softmax of fp32 scores -> single fp16 probabilities
__global__ __launch_bounds__(256) void softmax_f16(const float* __restrict__ S,
                                                   fp16* __restrict__ Ph)
{
    const float* row = S + (size_t)blockIdx.x * SEQ;
    const int tid = threadIdx.x;
    __shared__ float red[8];

    float v[8];
    #pragma unroll
    for (int i = 0; i < 8; i++) v[i] = row[tid + i * 256];

    float m = v[0];
    #pragma unroll
    for (int i = 1; i < 8; i++) m = fmaxf(m, v[i]);
    #pragma unroll
    for (int o = 16; o; o >>= 1) m = fmaxf(m, __shfl_xor_sync(0xffffffffu, m, o));
    if ((tid & 31) == 0) red[tid >> 5] = m;
    __syncthreads();
    float mx = red[0];
    #pragma unroll
    for (int w = 1; w < 8; w++) mx = fmaxf(mx, red[w]);
    __syncthreads();

    float s = 0.f;
    #pragma unroll
    for (int i = 0; i < 8; i++) { v[i] = __expf(v[i] - mx); s += v[i]; }
    #pragma unroll
    for (int o = 16; o; o >>= 1) s += __shfl_xor_sync(0xffffffffu, s, o);
    if ((tid & 31) == 0) red[tid >> 5] = s;
    __syncthreads();
    float tot = red[0];
    #pragma unroll
    for (int w = 1; w < 8; w++) tot += red[w];
    const float inv = 1.0f / tot;

    const size_t ro = (size_t)blockIdx.x * SEQ;
    #pragma unroll
    for (int i = 0; i < 8; i++)
        Ph[ro + tid + i * 256] = __float2half(v[i] * inv);
}

// ---------------- launcher ----------------
extern "C" void kernel_launch(void* const* d_in, const int* in_sizes, int n_in,
                              void* d_out, int out_size)
{
    const float* x  = (const float*)d_in[0];
    const float* Wq = (const float*)d_in[1];
    const float* bq = (const float*)d_in[2];
    const float* Wk = (const float*)d_in[3];
    const float* bk = (const float*)d_in[4];
    const float* Wv = (const float*)d_in[5];
    const float* bv = (const float*)d_in[6];
    float* out = (float*)d_out;

    fp16 *xhi, *xlo, *wt, *qkvhi, *qlo, *vt, *phi;
    float *s, *bias;
    cudaGetSymbolAddress((void**)&xhi, g_xhi);     cudaGetSymbolAddress((void**)&xlo, g_xlo);
    cudaGetSymbolAddress((void**)&wt, g_wt);
    cudaGetSymbolAddress((void**)&qkvhi, g_qkvhi); cudaGetSymbolAddress((void**)&qlo, g_qlo);
    cudaGetSymbolAddress((void**)&vt, g_vt);
    cudaGetSymbolAddress((void**)&phi, g_phi);
    cudaGetSymbolAddress((void**)&s, g_s);         cudaGetSymbolAddress((void**)&bias, g_bias);

    const int SMEM2 = 2 * 3 * TILE_B;   // 96 KB (2 stages x 3 tiles)
    const int SMEM1 = 3 * 2 * TILE_B;   // 96 KB (3 stages x 2 tiles)
    cudaFuncSetAttribute(gemmw<2>, cudaFuncAttributeMaxDynamicSharedMemorySize, SMEM2);
    cudaFuncSetAttribute(gemmw<1>, cudaFuncAttributeMaxDynamicSharedMemorySize, SMEM1);

    const int M = BATCH * SEQ;

    // 1. split x; transpose W (single fp16); concat bias
    split_f16<<<(M * DM / 4 + 255) / 256, 256>>>(x, xhi, xlo, M * DM / 4);
    transpose_w_f16<<<dim3(DM / 32, DM / 32, 3), dim3(32, 8)>>>(Wq, Wk, Wv, wt);
    concat_bias<<<(3 * DM + 255) / 256, 256>>>(bq, bk, bv, bias);

    // 2. fused QKV projection: q -> split hi/lo, k|v -> single fp16
    gemmw<2><<<dim3(3 * DM / 128, M / 128, 1), 256, SMEM2>>>(
        xhi, xlo, wt, bias, 1.f,
        nullptr, qkvhi, qlo,
        DM, DM, DM, DM, 3 * DM, DM, DM, 0, 0, 0, 0);

    // 3. V^T (single fp16)
    transpose_f16<<<dim3(DM / 32, SEQ / 32, BATCH), dim3(32, 8)>>>(qkvhi + 2 * DM, vt, 3 * DM);

    // 4. scores = scale * Q @ K^T (fp32 out); A = q hi/lo, B = k single
    gemmw<2><<<dim3(SEQ / 128, SEQ / 128, BATCH), 256, SMEM2>>>(
        qkvhi, qlo, qkvhi + DM, nullptr, 0.03125f,
        s, nullptr, nullptr,
        DM, 3 * DM, DM, 3 * DM, SEQ, 0, 0,
        (size_t)SEQ * 3 * DM, (size_t)SEQ * DM, (size_t)SEQ * 3 * DM, (size_t)SEQ * SEQ);

    // 5. softmax -> single fp16 probs
    softmax_f16<<<BATCH * SEQ, 256>>>(s, phi);

    // 6. out = attn @ V (fp32 out); A = p single, B = v^t single
    gemmw<1><<<dim3(DM / 128, SEQ / 128, BATCH), 256, SMEM1>>>(
        phi, nullptr, vt, nullptr, 1.f,
        out, nullptr, nullptr,
        SEQ, SEQ, 0, SEQ, DM, 0, 0,
        (size_t)SEQ * SEQ, 0, (size_t)DM * SEQ, (size_t)SEQ * DM);
}

// round 8
// speedup vs baseline: 5.5129x; 1.1489x over previous
#include <cuda_runtime.h>
#include <cuda_fp16.h>
#include <stdint.h>

#define BATCH 4
#define SEQ   2048
#define DM    1024
typedef __half fp16;

// ---------------- scratch (__device__ globals; no allocation) ----------------
__device__ fp16 g_xhi[(size_t)BATCH*SEQ*DM];
__device__ fp16 g_xlo[(size_t)BATCH*SEQ*DM];
__device__ fp16 g_wt[(size_t)3*DM*DM];            // W^T single fp16: [3*DM][DM]
__device__ float g_bias[3*DM];
__device__ fp16 g_qkvhi[(size_t)BATCH*SEQ*3*DM];  // [B*S][3DM]: q | k | v (single fp16)
__device__ fp16 g_vt[(size_t)BATCH*DM*SEQ];       // V^T single
__device__ float g_s[(size_t)BATCH*SEQ*SEQ];      // scores fp32
__device__ fp16 g_phi[(size_t)BATCH*SEQ*SEQ];     // attn probs (single fp16)

// ---------------- helpers ----------------
__device__ __forceinline__ uint32_t s2u(const void* p) {
    uint32_t a;
    asm("{ .reg .u64 t; cvta.to.shared.u64 t, %1; cvt.u32.u64 %0, t; }" : "=r"(a) : "l"(p));
    return a;
}
__device__ __forceinline__ void ldsm4(uint32_t* r, uint32_t addr) {
    asm volatile("ldmatrix.sync.aligned.m8n8.x4.shared.b16 {%0,%1,%2,%3}, [%4];"
                 : "=r"(r[0]), "=r"(r[1]), "=r"(r[2]), "=r"(r[3]) : "r"(addr));
}
__device__ __forceinline__ void mma16816(float* d, const uint32_t* a, uint32_t b0, uint32_t b1) {
    asm volatile(
        "mma.sync.aligned.m16n8k16.row.col.f32.f16.f16.f32 "
        "{%0,%1,%2,%3}, {%4,%5,%6,%7}, {%8,%9}, {%0,%1,%2,%3};"
        : "+f"(d[0]), "+f"(d[1]), "+f"(d[2]), "+f"(d[3])
        : "r"(a[0]), "r"(a[1]), "r"(a[2]), "r"(a[3]), "r"(b0), "r"(b1));
}

// ---------------- HMMA GEMM: C = scale*(A@B^T) [+bias] ----------------
// NPROD=2: A split hi/lo (2-product). NPROD=1: A single fp16.
// B single fp16 [N,K]. Out fp32 Cf OR fp16 Chi.
// CTA 128x128, BK=64, 256 threads (8 warps, warp tile 32x64), 2 CTAs/SM.
// Stages: NPROD==2 -> 2 (96 KB), NPROD==1 -> 3 (96 KB).
#define BK      64
#define TILE_B  16384                    // 128 rows * 128B

template<int NPROD>
__global__ __launch_bounds__(256, 2) void gemmw(
    const fp16* __restrict__ Ahi, const fp16* __restrict__ Alo,
    const fp16* __restrict__ B,
    const float* __restrict__ bias, float scale,
    float* __restrict__ Cf, fp16* __restrict__ Chi,
    int K, int lda, int ldalo, int ldb, int ldc,
    size_t sA, size_t sAlo, size_t sB, size_t sC)
{
    constexpr int NT = NPROD + 1;            // tiles per stage
    constexpr int NSTG = (NPROD == 2) ? 2 : 3;
    constexpr uint32_t STAGE_B = NT * TILE_B;
    extern __shared__ char smem[];
    const uint32_t sb = s2u(smem);
    const int tid = threadIdx.x;
    const int wid = tid >> 5, lane = tid & 31;
    const int wm = wid & 3, wn = wid >> 2;           // warp grid 4 (m) x 2 (n)
    const int m0 = blockIdx.y * 128, n0 = blockIdx.x * 128;
    const int NC = K / BK;

    const fp16* bAhi = Ahi + (size_t)blockIdx.z * sA   + (size_t)m0 * lda;
    const fp16* bAlo = (NPROD == 2) ? Alo + (size_t)blockIdx.z * sAlo + (size_t)m0 * ldalo : nullptr;
    const fp16* bB   = B   + (size_t)blockIdx.z * sB   + (size_t)n0 * ldb;

    auto load_chunk = [&](int c) {
        const uint32_t stg = sb + (uint32_t)(c % NSTG) * STAGE_B;
        const int k0 = c * BK;
        #pragma unroll
        for (int i = 0; i < 4 * NT; i++) {
            const int t = i >> 2;                       // 0: Ahi, [1: Alo,] last: B
            const int sub = tid + (i & 3) * 256;        // 0..1023
            const int row = sub >> 3, col = sub & 7;    // 128 rows x 8 16B-cols
            const int ld = (t == 0) ? lda : (t == NT - 1) ? ldb : ldalo;
            const fp16* src = (t == 0 ? bAhi : t == NT - 1 ? bB : bAlo)
                              + (size_t)row * ld + k0 + col * 8;
            uint32_t off = (uint32_t)(row * 128 + col * 16);
            uint32_t dst = stg + (uint32_t)t * TILE_B + (off ^ ((off >> 3) & 0x70));
            asm volatile("cp.async.cg.shared.global [%0], [%1], 16;" :: "r"(dst), "l"(src) : "memory");
        }
        asm volatile("cp.async.commit_group;" ::: "memory");
    };

    // per-lane ldmatrix addressing (SW128 rows of 128B)
    const int rlane = (lane & 7) + ((lane >> 3) & 1) * 8;
    const uint32_t xlane = (uint32_t)((rlane & 7) * 16);
    const uint32_t kbl = (uint32_t)((lane >> 4) * 16);
    uint32_t aoff[2], boff[4], kx[4];
    #pragma unroll
    for (int mf = 0; mf < 2; mf++) aoff[mf] = (uint32_t)((wm * 32 + mf * 16 + rlane) << 7);
    #pragma unroll
    for (int g = 0; g < 4; g++) boff[g] = (uint32_t)((wn * 64 + g * 16 + rlane) << 7);
    #pragma unroll
    for (int ks = 0; ks < 4; ks++) kx[ks] = ((uint32_t)(ks * 32) + kbl) ^ xlane;

    float acc[2][8][4] = {};

    #pragma unroll
    for (int p = 0; p < NSTG - 1; p++)
        if (p < NC) load_chunk(p);

    for (int c = 0; c < NC; ++c) {
        if (c + NSTG - 1 < NC) {
            if (NSTG == 3) asm volatile("cp.async.wait_group 1;" ::: "memory");
            else           asm volatile("cp.async.wait_group 0;" ::: "memory");
        } else {
            asm volatile("cp.async.wait_group 0;" ::: "memory");
        }
        __syncthreads();                       // chunk c visible; oldest stage free
        if (c + NSTG - 1 < NC) load_chunk(c + NSTG - 1);

        const uint32_t stg = sb + (uint32_t)(c % NSTG) * STAGE_B;
        const uint32_t sAh = stg;
        const uint32_t sAl = stg + TILE_B;                    // valid when NPROD==2
        const uint32_t sB_ = stg + (uint32_t)(NT - 1) * TILE_B;

        #pragma unroll
        for (int ks = 0; ks < 4; ks++) {
            uint32_t ah[2][4], al[2][4], bf[8][2];
            ldsm4(ah[0], sAh + aoff[0] + kx[ks]);
            ldsm4(ah[1], sAh + aoff[1] + kx[ks]);
            #pragma unroll
            for (int g = 0; g < 4; g++) {
                uint32_t t[4];
                ldsm4(t, sB_ + boff[g] + kx[ks]);
                bf[2*g][0] = t[0]; bf[2*g+1][0] = t[1];
                bf[2*g][1] = t[2]; bf[2*g+1][1] = t[3];
            }
            if (NPROD == 2) {                   // issued early; hidden by hi-MMAs
                ldsm4(al[0], sAl + aoff[0] + kx[ks]);
                ldsm4(al[1], sAl + aoff[1] + kx[ks]);
            }
            #pragma unroll
            for (int mf = 0; mf < 2; mf++)
                #pragma unroll
                for (int nf = 0; nf < 8; nf++)
                    mma16816(acc[mf][nf], ah[mf], bf[nf][0], bf[nf][1]);
            if (NPROD == 2) {
                #pragma unroll
                for (int mf = 0; mf < 2; mf++)
                    #pragma unroll
                    for (int nf = 0; nf < 8; nf++)
                        mma16816(acc[mf][nf], al[mf], bf[nf][0], bf[nf][1]);
            }
        }
    }

    // ---------------- epilogue ----------------
    const size_t cb = (size_t)blockIdx.z * sC;
    #pragma unroll
    for (int mf = 0; mf < 2; mf++) {
        #pragma unroll
        for (int nf = 0; nf < 8; nf++) {
            const int m = m0 + wm * 32 + mf * 16 + (lane >> 2);
            const int n = n0 + wn * 64 + nf * 8 + 2 * (lane & 3);
            const float b0 = bias ? bias[n] : 0.f;
            const float b1 = bias ? bias[n + 1] : 0.f;
            float v00 = acc[mf][nf][0] * scale + b0;
            float v01 = acc[mf][nf][1] * scale + b1;
            float v10 = acc[mf][nf][2] * scale + b0;
            float v11 = acc[mf][nf][3] * scale + b1;
            if (Cf) {
                float2 o0 = {v00, v01}, o1 = {v10, v11};
                *reinterpret_cast<float2*>(Cf + cb + (size_t)m * ldc + n)       = o0;
                *reinterpret_cast<float2*>(Cf + cb + (size_t)(m + 8) * ldc + n) = o1;
            } else {
                __half2 ph0 = {__float2half(v00), __float2half(v01)};
                __half2 ph1 = {__float2half(v10), __float2half(v11)};
                *reinterpret_cast<__half2*>(Chi + cb + (size_t)m * ldc + n)       = ph0;
                *reinterpret_cast<__half2*>(Chi + cb + (size_t)(m + 8) * ldc + n) = ph1;
            }
        }
    }
}

// ---------------- aux kernels ----------------
__global__ __launch_bounds__(256) void split_f16(const float* __restrict__ in,
                                                 fp16* __restrict__ hi, fp16* __restrict__ lo, int n4)
{
    int i = blockIdx.x * 256 + threadIdx.x;
    if (i >= n4) return;
    float4 v = reinterpret_cast<const float4*>(in)[i];
    __align__(8) fp16 h[4];
    __align__(8) fp16 l[4];
    float f[4] = {v.x, v.y, v.z, v.w};
    #pragma unroll
    for (int j = 0; j < 4; j++) {
        h[j] = __float2half(f[j]);
        l[j] = __float2half(f[j] - __half2float(h[j]));
    }
    reinterpret_cast<uint2*>(hi)[i] = *reinterpret_cast<uint2*>(h);
    reinterpret_cast<uint2*>(lo)[i] = *reinterpret_cast<uint2*>(l);
}

__global__ void concat_bias(const float* a, const float* b, const float* c, float* o)
{
    int i = blockIdx.x * 256 + threadIdx.x;
    if (i < DM)            o[i] = a[i];
    else if (i < 2 * DM)   o[i] = b[i - DM];
    else if (i < 3 * DM)   o[i] = c[i - 2 * DM];
}

// W [K=DM, N=DM] fp32 -> wt fp16 [N, K] (transposed, single-rounded), z selects Wq/Wk/Wv
__global__ void transpose_w_f16(const float* __restrict__ Wq, const float* __restrict__ Wk,
                                const float* __restrict__ Wv, fp16* __restrict__ wt)
{
    __shared__ float t[32][33];
    const float* W = blockIdx.z == 0 ? Wq : blockIdx.z == 1 ? Wk : Wv;
    fp16* o = wt + (size_t)blockIdx.z * DM * DM;
    const int n0 = blockIdx.x * 32, k0 = blockIdx.y * 32;
    const int tx = threadIdx.x, ty = threadIdx.y;
    #pragma unroll
    for (int r = 0; r < 4; r++)
        t[ty + 8 * r][tx] = W[(size_t)(k0 + ty + 8 * r) * DM + n0 + tx];
    __syncthreads();
    #pragma unroll
    for (int r = 0; r < 4; r++)
        o[(size_t)(n0 + ty + 8 * r) * DM + k0 + tx] = __float2half(t[tx][ty + 8 * r]);
}

// V slice of [B][SEQ][3*DM] (fp16, stride ldin) -> [B][DM][SEQ] fp16 transpose
__global__ void transpose_f16(const fp16* __restrict__ in, fp16* __restrict__ out, int ldin)
{
    __shared__ fp16 t[32][33];
    const size_t ib = (size_t)blockIdx.z * SEQ * ldin;
    const size_t ob = (size_t)blockIdx.z * DM * SEQ;
    const int s0 = blockIdx.y * 32, d0 = blockIdx.x * 32;
    const int tx = threadIdx.x, ty = threadIdx.y;
    #pragma unroll
    for (int r = 0; r < 4; r++)
        t[ty + 8 * r][tx] = in[ib + (size_t)(s0 + ty + 8 * r) * ldin + d0 + tx];
    __syncthreads();
    #pragma unroll
    for (int r = 0; r < 4; r++)
        out[ob + (size_t)(d0 + ty + 8 * r) * SEQ + s0 + tx] = t[tx][ty + 8 * r];
}

// row softmax of fp32 scores -> single fp16 probabilities
__global__ __launch_bounds__(256) void softmax_f16(const float* __restrict__ S,
                                                   fp16* __restrict__ Ph)
{
    const float* row = S + (size_t)blockIdx.x * SEQ;
    const int tid = threadIdx.x;
    __shared__ float red[8];

    float v[8];
    #pragma unroll
    for (int i = 0; i < 8; i++) v[i] = row[tid + i * 256];

    float m = v[0];
    #pragma unroll
    for (int i = 1; i < 8; i++) m = fmaxf(m, v[i]);
    #pragma unroll
    for (int o = 16; o; o >>= 1) m = fmaxf(m, __shfl_xor_sync(0xffffffffu, m, o));
    if ((tid & 31) == 0) red[tid >> 5] = m;
    __syncthreads();
    float mx = red[0];
    #pragma unroll
    for (int w = 1; w < 8; w++) mx = fmaxf(mx, red[w]);
    __syncthreads();

    float s = 0.f;
    #pragma unroll
    for (int i = 0; i < 8; i++) { v[i] = __expf(v[i] - mx); s += v[i]; }
    #pragma unroll
    for (int o = 16; o; o >>= 1) s += __shfl_xor_sync(0xffffffffu, s, o);
    if ((tid & 31) == 0) red[tid >> 5] = s;
    __syncthreads();
    float tot = red[0];
    #pragma unroll
    for (int w = 1; w < 8; w++) tot += red[w];
    const float inv = 1.0f / tot;

    const size_t ro = (size_t)blockIdx.x * SEQ;
    #pragma unroll
    for (int i = 0; i < 8; i++)
        Ph[ro + tid + i * 256] = __float2half(v[i] * inv);
}

// ---------------- launcher ----------------
extern "C" void kernel_launch(void* const* d_in, const int* in_sizes, int n_in,
                              void* d_out, int out_size)
{
    const float* x  = (const float*)d_in[0];
    const float* Wq = (const float*)d_in[1];
    const float* bq = (const float*)d_in[2];
    const float* Wk = (const float*)d_in[3];
    const float* bk = (const float*)d_in[4];
    const float* Wv = (const float*)d_in[5];
    const float* bv = (const float*)d_in[6];
    float* out = (float*)d_out;

    fp16 *xhi, *xlo, *wt, *qkvhi, *vt, *phi;
    float *s, *bias;
    cudaGetSymbolAddress((void**)&xhi, g_xhi);     cudaGetSymbolAddress((void**)&xlo, g_xlo);
    cudaGetSymbolAddress((void**)&wt, g_wt);
    cudaGetSymbolAddress((void**)&qkvhi, g_qkvhi);
    cudaGetSymbolAddress((void**)&vt, g_vt);
    cudaGetSymbolAddress((void**)&phi, g_phi);
    cudaGetSymbolAddress((void**)&s, g_s);         cudaGetSymbolAddress((void**)&bias, g_bias);

    const int SMEM2 = 2 * 3 * TILE_B;   // 96 KB (2 stages x 3 tiles)
    const int SMEM1 = 3 * 2 * TILE_B;   // 96 KB (3 stages x 2 tiles)
    cudaFuncSetAttribute(gemmw<2>, cudaFuncAttributeMaxDynamicSharedMemorySize, SMEM2);
    cudaFuncSetAttribute(gemmw<1>, cudaFuncAttributeMaxDynamicSharedMemorySize, SMEM1);

    const int M = BATCH * SEQ;

    // 1. split x; transpose W (single fp16); concat bias
    split_f16<<<(M * DM / 4 + 255) / 256, 256>>>(x, xhi, xlo, M * DM / 4);
    transpose_w_f16<<<dim3(DM / 32, DM / 32, 3), dim3(32, 8)>>>(Wq, Wk, Wv, wt);
    concat_bias<<<(3 * DM + 255) / 256, 256>>>(bq, bk, bv, bias);

    // 2. fused QKV projection (x split 2-product), all outputs single fp16
    gemmw<2><<<dim3(3 * DM / 128, M / 128, 1), 256, SMEM2>>>(
        xhi, xlo, wt, bias, 1.f,
        nullptr, qkvhi,
        DM, DM, DM, DM, 3 * DM, 0, 0, 0, 0);

    // 3. V^T (single fp16)
    transpose_f16<<<dim3(DM / 32, SEQ / 32, BATCH), dim3(32, 8)>>>(qkvhi + 2 * DM, vt, 3 * DM);

    // 4. scores = scale * Q @ K^T (fp32 out); SINGLE-product (q_lo dropped)
    gemmw<1><<<dim3(SEQ / 128, SEQ / 128, BATCH), 256, SMEM1>>>(
        qkvhi, nullptr, qkvhi + DM, nullptr, 0.03125f,
        s, nullptr,
        DM, 3 * DM, 0, 3 * DM, SEQ,
        (size_t)SEQ * 3 * DM, 0, (size_t)SEQ * 3 * DM, (size_t)SEQ * SEQ);

    // 5. softmax -> single fp16 probs
    softmax_f16<<<BATCH * SEQ, 256>>>(s, phi);

    // 6. out = attn @ V (fp32 out), single-product
    gemmw<1><<<dim3(DM / 128, SEQ / 128, BATCH), 256, SMEM1>>>(
        phi, nullptr, vt, nullptr, 1.f,
        out, nullptr,
        SEQ, SEQ, 0, SEQ, DM,
        (size_t)SEQ * SEQ, 0, (size_t)DM * SEQ, (size_t)SEQ * DM);
}

// round 9
// speedup vs baseline: 7.2568x; 1.3163x over previous
#include <cuda_runtime.h>
#include <cuda_fp16.h>
#include <stdint.h>

#define BATCH 4
#define SEQ   2048
#define DM    1024
typedef __half fp16;

// ---------------- scratch (__device__ globals; no allocation) ----------------
__device__ fp16 g_x16[(size_t)BATCH*SEQ*DM];      // x single fp16
__device__ fp16 g_wt[(size_t)3*DM*DM];            // W^T single fp16: [3*DM][DM]
__device__ float g_bias[3*DM];
__device__ fp16 g_qkv[(size_t)BATCH*SEQ*3*DM];    // [B*S][3DM]: q | k | v
__device__ fp16 g_vt[(size_t)BATCH*DM*SEQ];       // V^T
__device__ float g_s[(size_t)BATCH*SEQ*SEQ];      // scores fp32
__device__ fp16 g_p[(size_t)BATCH*SEQ*SEQ];       // attn probs fp16

// ---------------- helpers ----------------
__device__ __forceinline__ uint32_t s2u(const void* p) {
    uint32_t a;
    asm("{ .reg .u64 t; cvta.to.shared.u64 t, %1; cvt.u32.u64 %0, t; }" : "=r"(a) : "l"(p));
    return a;
}
__device__ __forceinline__ void ldsm4(uint32_t* r, uint32_t addr) {
    asm volatile("ldmatrix.sync.aligned.m8n8.x4.shared.b16 {%0,%1,%2,%3}, [%4];"
                 : "=r"(r[0]), "=r"(r[1]), "=r"(r[2]), "=r"(r[3]) : "r"(addr));
}
__device__ __forceinline__ void mma16816(float* d, const uint32_t* a, uint32_t b0, uint32_t b1) {
    asm volatile(
        "mma.sync.aligned.m16n8k16.row.col.f32.f16.f16.f32 "
        "{%0,%1,%2,%3}, {%4,%5,%6,%7}, {%8,%9}, {%0,%1,%2,%3};"
        : "+f"(d[0]), "+f"(d[1]), "+f"(d[2]), "+f"(d[3])
        : "r"(a[0]), "r"(a[1]), "r"(a[2]), "r"(a[3]), "r"(b0), "r"(b1));
}

// ---------------- HMMA GEMM: C = scale*(A@B^T) [+bias], single fp16 product ----------------
// A [M,K] stride lda, B [N,K] stride ldb, out fp32 Cf OR fp16 Chi (stride ldc).
// CTA 128x128, BK=64, 256 threads (8 warps, warp tile 32x64), 3 stages, 2 CTAs/SM.
#define BK      64
#define TILE_B  16384                    // 128 rows * 128B
#define NSTG    3
#define GSMEM   (NSTG * 2 * TILE_B)      // 96 KB

__global__ __launch_bounds__(256, 2) void gemmw(
    const fp16* __restrict__ A, const fp16* __restrict__ B,
    const float* __restrict__ bias, float scale,
    float* __restrict__ Cf, fp16* __restrict__ Chi,
    int K, int lda, int ldb, int ldc,
    size_t sA, size_t sB, size_t sC)
{
    extern __shared__ char smem[];
    const uint32_t sb = s2u(smem);
    const int tid = threadIdx.x;
    const int wid = tid >> 5, lane = tid & 31;
    const int wm = wid & 3, wn = wid >> 2;           // warp grid 4 (m) x 2 (n)
    const int m0 = blockIdx.y * 128, n0 = blockIdx.x * 128;
    const int NC = K / BK;

    const fp16* bA = A + (size_t)blockIdx.z * sA + (size_t)m0 * lda;
    const fp16* bB = B + (size_t)blockIdx.z * sB + (size_t)n0 * ldb;

    auto load_chunk = [&](int c) {
        const uint32_t stg = sb + (uint32_t)(c % NSTG) * (2 * TILE_B);
        const int k0 = c * BK;
        #pragma unroll
        for (int i = 0; i < 8; i++) {
            const int t = i >> 2;                       // 0: A, 1: B
            const int sub = tid + (i & 3) * 256;        // 0..1023
            const int row = sub >> 3, col = sub & 7;    // 128 rows x 8 16B-cols
            const int ld = t ? ldb : lda;
            const fp16* src = (t ? bB : bA) + (size_t)row * ld + k0 + col * 8;
            uint32_t off = (uint32_t)(row * 128 + col * 16);
            uint32_t dst = stg + (uint32_t)t * TILE_B + (off ^ ((off >> 3) & 0x70));
            asm volatile("cp.async.cg.shared.global [%0], [%1], 16;" :: "r"(dst), "l"(src) : "memory");
        }
        asm volatile("cp.async.commit_group;" ::: "memory");
    };

    // per-lane ldmatrix addressing (SW128 rows of 128B)
    const int rlane = (lane & 7) + ((lane >> 3) & 1) * 8;
    const uint32_t xlane = (uint32_t)((rlane & 7) * 16);
    const uint32_t kbl = (uint32_t)((lane >> 4) * 16);
    uint32_t aoff[2], boff[4], kx[4];
    #pragma unroll
    for (int mf = 0; mf < 2; mf++) aoff[mf] = (uint32_t)((wm * 32 + mf * 16 + rlane) << 7);
    #pragma unroll
    for (int g = 0; g < 4; g++) boff[g] = (uint32_t)((wn * 64 + g * 16 + rlane) << 7);
    #pragma unroll
    for (int ks = 0; ks < 4; ks++) kx[ks] = ((uint32_t)(ks * 32) + kbl) ^ xlane;

    float acc[2][8][4] = {};

    load_chunk(0);
    if (NC > 1) load_chunk(1);

    for (int c = 0; c < NC; ++c) {
        if (c + 2 < NC) asm volatile("cp.async.wait_group 1;" ::: "memory");
        else            asm volatile("cp.async.wait_group 0;" ::: "memory");
        __syncthreads();                       // chunk c visible; oldest stage free
        if (c + 2 < NC) load_chunk(c + 2);

        const uint32_t stg = sb + (uint32_t)(c % NSTG) * (2 * TILE_B);
        const uint32_t sA_ = stg, sB_ = stg + TILE_B;

        #pragma unroll
        for (int ks = 0; ks < 4; ks++) {
            uint32_t ah[2][4], bf[8][2];
            ldsm4(ah[0], sA_ + aoff[0] + kx[ks]);
            ldsm4(ah[1], sA_ + aoff[1] + kx[ks]);
            #pragma unroll
            for (int g = 0; g < 4; g++) {
                uint32_t t[4];
                ldsm4(t, sB_ + boff[g] + kx[ks]);
                bf[2*g][0] = t[0]; bf[2*g+1][0] = t[1];
                bf[2*g][1] = t[2]; bf[2*g+1][1] = t[3];
            }
            #pragma unroll
            for (int mf = 0; mf < 2; mf++)
                #pragma unroll
                for (int nf = 0; nf < 8; nf++)
                    mma16816(acc[mf][nf], ah[mf], bf[nf][0], bf[nf][1]);
        }
    }

    // ---------------- epilogue ----------------
    const size_t cb = (size_t)blockIdx.z * sC;
    #pragma unroll
    for (int mf = 0; mf < 2; mf++) {
        #pragma unroll
        for (int nf = 0; nf < 8; nf++) {
            const int m = m0 + wm * 32 + mf * 16 + (lane >> 2);
            const int n = n0 + wn * 64 + nf * 8 + 2 * (lane & 3);
            const float b0 = bias ? bias[n] : 0.f;
            const float b1 = bias ? bias[n + 1] : 0.f;
            float v00 = acc[mf][nf][0] * scale + b0;
            float v01 = acc[mf][nf][1] * scale + b1;
            float v10 = acc[mf][nf][2] * scale + b0;
            float v11 = acc[mf][nf][3] * scale + b1;
            if (Cf) {
                float2 o0 = {v00, v01}, o1 = {v10, v11};
                *reinterpret_cast<float2*>(Cf + cb + (size_t)m * ldc + n)       = o0;
                *reinterpret_cast<float2*>(Cf + cb + (size_t)(m + 8) * ldc + n) = o1;
            } else {
                __half2 ph0 = {__float2half(v00), __float2half(v01)};
                __half2 ph1 = {__float2half(v10), __float2half(v11)};
                *reinterpret_cast<__half2*>(Chi + cb + (size_t)m * ldc + n)       = ph0;
                *reinterpret_cast<__half2*>(Chi + cb + (size_t)(m + 8) * ldc + n) = ph1;
            }
        }
    }
}

// ---------------- aux kernels ----------------
__global__ __launch_bounds__(256) void conv_f16(const float* __restrict__ in,
                                                fp16* __restrict__ o, int n4)
{
    int i = blockIdx.x * 256 + threadIdx.x;
    if (i >= n4) return;
    float4 v = reinterpret_cast<const float4*>(in)[i];
    __align__(8) fp16 h[4];
    h[0] = __float2half(v.x); h[1] = __float2half(v.y);
    h[2] = __float2half(v.z); h[3] = __float2half(v.w);
    reinterpret_cast<uint2*>(o)[i] = *reinterpret_cast<uint2*>(h);
}

__global__ void concat_bias(const float* a, const float* b, const float* c, float* o)
{
    int i = blockIdx.x * 256 + threadIdx.x;
    if (i < DM)            o[i] = a[i];
    else if (i < 2 * DM)   o[i] = b[i - DM];
    else if (i < 3 * DM)   o[i] = c[i - 2 * DM];
}

// W [K=DM, N=DM] fp32 -> wt fp16 [N, K] (transposed), z selects Wq/Wk/Wv
__global__ void transpose_w_f16(const float* __restrict__ Wq, const float* __restrict__ Wk,
                                const float* __restrict__ Wv, fp16* __restrict__ wt)
{
    __shared__ float t[32][33];
    const float* W = blockIdx.z == 0 ? Wq : blockIdx.z == 1 ? Wk : Wv;
    fp16* o = wt + (size_t)blockIdx.z * DM * DM;
    const int n0 = blockIdx.x * 32, k0 = blockIdx.y * 32;
    const int tx = threadIdx.x, ty = threadIdx.y;
    #pragma unroll
    for (int r = 0; r < 4; r++)
        t[ty + 8 * r][tx] = W[(size_t)(k0 + ty + 8 * r) * DM + n0 + tx];
    __syncthreads();
    #pragma unroll
    for (int r = 0; r < 4; r++)
        o[(size_t)(n0 + ty + 8 * r) * DM + k0 + tx] = __float2half(t[tx][ty + 8 * r]);
}

// V slice of [B][SEQ][3*DM] (fp16, stride ldin) -> [B][DM][SEQ] fp16 transpose
__global__ void transpose_f16(const fp16* __restrict__ in, fp16* __restrict__ out, int ldin)
{
    __shared__ fp16 t[32][33];
    const size_t ib = (size_t)blockIdx.z * SEQ * ldin;
    const size_t ob = (size_t)blockIdx.z * DM * SEQ;
    const int s0 = blockIdx.y * 32, d0 = blockIdx.x * 32;
    const int tx = threadIdx.x, ty = threadIdx.y;
    #pragma unroll
    for (int r = 0; r < 4; r++)
        t[ty + 8 * r][tx] = in[ib + (size_t)(s0 + ty + 8 * r) * ldin + d0 + tx];
    __syncthreads();
    #pragma unroll
    for (int r = 0; r < 4; r++)
        out[ob + (size_t)(d0 + ty + 8 * r) * SEQ + s0 + tx] = t[tx][ty + 8 * r];
}

// row softmax of fp32 scores -> fp16 probabilities
__global__ __launch_bounds__(256) void softmax_f16(const float* __restrict__ S,
                                                   fp16* __restrict__ Ph)
{
    const float* row = S + (size_t)blockIdx.x * SEQ;
    const int tid = threadIdx.x;
    __shared__ float red[8];

    float v[8];
    #pragma unroll
    for (int i = 0; i < 8; i++) v[i] = row[tid + i * 256];

    float m = v[0];
    #pragma unroll
    for (int i = 1; i < 8; i++) m = fmaxf(m, v[i]);
    #pragma unroll
    for (int o = 16; o; o >>= 1) m = fmaxf(m, __shfl_xor_sync(0xffffffffu, m, o));
    if ((tid & 31) == 0) red[tid >> 5] = m;
    __syncthreads();
    float mx = red[0];
    #pragma unroll
    for (int w = 1; w < 8; w++) mx = fmaxf(mx, red[w]);
    __syncthreads();

    float s = 0.f;
    #pragma unroll
    for (int i = 0; i < 8; i++) { v[i] = __expf(v[i] - mx); s += v[i]; }
    #pragma unroll
    for (int o = 16; o; o >>= 1) s += __shfl_xor_sync(0xffffffffu, s, o);
    if ((tid & 31) == 0) red[tid >> 5] = s;
    __syncthreads();
    float tot = red[0];
    #pragma unroll
    for (int w = 1; w < 8; w++) tot += red[w];
    const float inv = 1.0f / tot;

    const size_t ro = (size_t)blockIdx.x * SEQ;
    #pragma unroll
    for (int i = 0; i < 8; i++)
        Ph[ro + tid + i * 256] = __float2half(v[i] * inv);
}

// ---------------- launcher ----------------
extern "C" void kernel_launch(void* const* d_in, const int* in_sizes, int n_in,
                              void* d_out, int out_size)
{
    const float* x  = (const float*)d_in[0];
    const float* Wq = (const float*)d_in[1];
    const float* bq = (const float*)d_in[2];
    const float* Wk = (const float*)d_in[3];
    const float* bk = (const float*)d_in[4];
    const float* Wv = (const float*)d_in[5];
    const float* bv = (const float*)d_in[6];
    float* out = (float*)d_out;

    fp16 *x16, *wt, *qkv, *vt, *p;
    float *s, *bias;
    cudaGetSymbolAddress((void**)&x16, g_x16);
    cudaGetSymbolAddress((void**)&wt, g_wt);
    cudaGetSymbolAddress((void**)&qkv, g_qkv);
    cudaGetSymbolAddress((void**)&vt, g_vt);
    cudaGetSymbolAddress((void**)&p, g_p);
    cudaGetSymbolAddress((void**)&s, g_s);
    cudaGetSymbolAddress((void**)&bias, g_bias);

    cudaFuncSetAttribute(gemmw, cudaFuncAttributeMaxDynamicSharedMemorySize, GSMEM);

    const int M = BATCH * SEQ;

    // 1. convert x; transpose W; concat bias
    conv_f16<<<(M * DM / 4 + 255) / 256, 256>>>(x, x16, M * DM / 4);
    transpose_w_f16<<<dim3(DM / 32, DM / 32, 3), dim3(32, 8)>>>(Wq, Wk, Wv, wt);
    concat_bias<<<(3 * DM + 255) / 256, 256>>>(bq, bk, bv, bias);

    // 2. fused QKV projection: [8192, 3072] = x16 @ wt^T + bias
    gemmw<<<dim3(3 * DM / 128, M / 128, 1), 256, GSMEM>>>(
        x16, wt, bias, 1.f,
        nullptr, qkv,
        DM, DM, DM, 3 * DM, 0, 0, 0);

    // 3. V^T
    transpose_f16<<<dim3(DM / 32, SEQ / 32, BATCH), dim3(32, 8)>>>(qkv + 2 * DM, vt, 3 * DM);

    // 4. scores = scale * Q @ K^T (fp32 out)
    gemmw<<<dim3(SEQ / 128, SEQ / 128, BATCH), 256, GSMEM>>>(
        qkv, qkv + DM, nullptr, 0.03125f,
        s, nullptr,
        DM, 3 * DM, 3 * DM, SEQ,
        (size_t)SEQ * 3 * DM, (size_t)SEQ * 3 * DM, (size_t)SEQ * SEQ);

    // 5. softmax -> fp16 probs
    softmax_f16<<<BATCH * SEQ, 256>>>(s, p);

    // 6. out = attn @ V (fp32 out)
    gemmw<<<dim3(DM / 128, SEQ / 128, BATCH), 256, GSMEM>>>(
        p, vt, nullptr, 1.f,
        out, nullptr,
        SEQ, SEQ, SEQ, DM,
        (size_t)SEQ * SEQ, (size_t)DM * SEQ, (size_t)SEQ * DM);
}